// round 4
// baseline (speedup 1.0000x reference)
#include <cuda_runtime.h>

#define NV   4096
#define NSV  256
#define BB   2
#define GXD  128
#define GYD  128
#define GZD  16
#define CC   128
#define NCL  20
#define NH   8
#define DHD  16
#define MAPSZ (BB*GXD*GYD*GZD)
#define EPSF 1e-5f
#define GQ   8

// ---------------- packed f32x2 helpers ----------------
typedef unsigned long long ull;
__device__ __forceinline__ ull pk(float lo, float hi) {
    ull r; asm("mov.b64 %0, {%1,%2};" : "=l"(r) : "f"(lo), "f"(hi)); return r;
}
__device__ __forceinline__ ull pk2(float2 f) { return pk(f.x, f.y); }
__device__ __forceinline__ void upk(float& lo, float& hi, ull v) {
    asm("mov.b64 {%0,%1}, %2;" : "=f"(lo), "=f"(hi) : "l"(v));
}
#define FMA2(d,a,b,c) asm("fma.rn.f32x2 %0, %1, %2, %3;" : "=l"(d) : "l"(a), "l"(b), "l"(c))

// ---------------- cp.async helpers ----------------
__device__ __forceinline__ unsigned smem_u32(const void* p) {
    unsigned a;
    asm("{ .reg .u64 t; cvta.to.shared.u64 t, %1; cvt.u32.u64 %0, t; }" : "=r"(a) : "l"(p));
    return a;
}
#define CPA16(dst, src) asm volatile("cp.async.cg.shared.global [%0], [%1], 16;" :: "r"(dst), "l"(src))
#define CPA_COMMIT()    asm volatile("cp.async.commit_group;")
#define CPA_WAIT(n)     asm volatile("cp.async.wait_group %0;" :: "n"(n))

// ---------------- device scratch ----------------
struct Acc { float cf[NSV*CC]; float s1[CC]; float s2[CC]; };
__device__ Acc  g_acc;
__device__ int4 g_unq[NSV];
__device__ int  g_sinv[NV];
__device__ float g_hid[NSV*CC];
__device__ float g_kT[CC*NSV];
__device__ float g_vT[CC*NSV];
__device__ float g_y[NV*CC];
__device__ int   g_map[MAPSZ];          // zero-init; stores n+1
__device__ float g_pweff[4*64];

// ================= k_prep: keys, unique, inverse, pbias BN fold ==========
__global__ void k_prep(const int* __restrict__ idx,
                       const float* __restrict__ pw1, const float* __restrict__ pb1,
                       const float* __restrict__ pg1, const float* __restrict__ pbe1) {
    __shared__ unsigned sflags[256];
    __shared__ unsigned short skeys[NV];
    __shared__ int sscan[256], srank[256];
    __shared__ long long wred[8];
    __shared__ double Si[9], Su[9], md[3], Cv[3][3];
    int t = threadIdx.x, lane = t & 31, wid = t >> 5;

    sflags[t] = 0u;
    __syncthreads();

    long long m[9] = {0,0,0,0,0,0,0,0,0};
    for (int i = t; i < NV; i += 256) {
        int4 p = ((const int4*)idx)[i];
        int key = ((p.x * 32 + (p.y >> 2)) * 32 + (p.z >> 2)) * 4 + (p.w >> 2);
        skeys[i] = (unsigned short)key;
        atomicOr(&sflags[key >> 5], 1u << (key & 31));
        g_map[((p.x * GXD + p.y) * GYD + p.z) * GZD + p.w] = i + 1;
        long long xs = p.y, ys = p.z, zs = p.w;
        m[0]+=xs; m[1]+=ys; m[2]+=zs; m[3]+=xs*xs; m[4]+=ys*ys; m[5]+=zs*zs;
        m[6]+=xs*ys; m[7]+=xs*zs; m[8]+=ys*zs;
    }
    __syncthreads();

    unsigned w = sflags[t];
    int cnt = __popc(w);
    sscan[t] = cnt; __syncthreads();
    for (int off = 1; off < 256; off <<= 1) {
        int v = (t >= off) ? sscan[t - off] : 0;
        __syncthreads(); sscan[t] += v; __syncthreads();
    }
    int excl = sscan[t] - cnt;
    srank[t] = excl;
    unsigned wb = w;
    while (wb) {
        int bit = __ffs(wb) - 1; wb &= wb - 1;
        int rank = excl + __popc(w & ((1u << bit) - 1u));
        int key = t * 32 + bit;
        int4 u;
        u.w = key & 3; u.z = (key >> 2) & 31; u.y = (key >> 7) & 31; u.x = key >> 12;
        g_unq[rank] = u;
    }
    __syncthreads();

    for (int i = t; i < NV; i += 256) {
        int key = skeys[i];
        g_sinv[i] = srank[key >> 5] + __popc(sflags[key >> 5] & ((1u << (key & 31)) - 1u));
    }

    for (int k = 0; k < 9; k++) {
        long long v = m[k];
        for (int o = 16; o; o >>= 1) v += __shfl_xor_sync(~0u, v, o);
        if (lane == 0) wred[wid] = v;
        __syncthreads();
        if (t == 0) { long long s = 0; for (int i = 0; i < 8; i++) s += wred[i]; Si[k] = (double)s; }
        __syncthreads();
    }
    {
        int4 u = g_unq[t];
        long long xs = u.y, ys = u.z, zs = u.w;
        long long mu9[9] = { xs, ys, zs, xs*xs, ys*ys, zs*zs, xs*ys, xs*zs, ys*zs };
        for (int k = 0; k < 9; k++) {
            long long v = mu9[k];
            for (int o = 16; o; o >>= 1) v += __shfl_xor_sync(~0u, v, o);
            if (lane == 0) wred[wid] = v;
            __syncthreads();
            if (t == 0) { long long s = 0; for (int i = 0; i < 8; i++) s += wred[i]; Su[k] = (double)s; }
            __syncthreads();
        }
    }
    if (t == 0) {
        double mi[3], mu_[3];
        for (int a = 0; a < 3; a++) {
            mi[a]  = Si[a] / (double)NV;
            mu_[a] = Su[a] / (double)NSV;
            md[a]  = mi[a] - mu_[a];
        }
        const int pid[3][3] = { {3,6,7}, {6,4,8}, {7,8,5} };
        for (int a = 0; a < 3; a++)
            for (int b = 0; b < 3; b++)
                Cv[a][b] = (Si[pid[a][b]] / (double)NV  - mi[a]  * mi[b])
                         + (Su[pid[a][b]] / (double)NSV - mu_[a] * mu_[b]);
    }
    __syncthreads();
    if (t < 64) {
        int j = t;
        double w3[3];
        for (int a = 0; a < 3; a++) w3[a] = (double)pw1[a*64 + j];
        double mu = md[0]*w3[0] + md[1]*w3[1] + md[2]*w3[2] + (double)pb1[j];
        double var = 0.0;
        for (int a = 0; a < 3; a++)
            for (int b = 0; b < 3; b++)
                var += w3[a] * Cv[a][b] * w3[b];
        float s = rsqrtf((float)var + EPSF) * pg1[j];
        for (int a = 0; a < 3; a++) g_pweff[a*64 + j] = (float)w3[a] * s;
        g_pweff[192 + j] = (float)((double)pb1[j] - mu) * s + pbe1[j];
    }
}

// ================= per-voxel softmax + scatter (4 rows/block) ==============
__global__ void k_sms(const float* __restrict__ feat) {
    int t = threadIdx.x;
    __shared__ float redm[4], reds[4];
    #pragma unroll
    for (int rr = 0; rr < 4; rr++) {
        int n = blockIdx.x * 4 + rr;
        float v = feat[n*CC + t];
        float m = v;
        for (int o = 16; o; o >>= 1) m = fmaxf(m, __shfl_xor_sync(~0u, m, o));
        if ((t & 31) == 0) redm[t >> 5] = m;
        __syncthreads();
        m = fmaxf(fmaxf(redm[0], redm[1]), fmaxf(redm[2], redm[3]));
        float e = __expf(v - m);
        float s = e;
        for (int o = 16; o; o >>= 1) s += __shfl_xor_sync(~0u, s, o);
        if ((t & 31) == 0) reds[t >> 5] = s;
        __syncthreads();
        s = reds[0] + reds[1] + reds[2] + reds[3];
        atomicAdd(&g_acc.cf[g_sinv[n]*CC + t], e / s);
        __syncthreads();
    }
}

// ================= gemm1 (cf@cw1+cb1) + BN stat atomics ====================
// grid 128, block 128: 2 rows x 64 col-threads (float2 weights)
__global__ void k_gemm1(const float* __restrict__ cw1, const float* __restrict__ cb1) {
    int t = threadIdx.x;
    int r = t >> 6, ct = t & 63, c0 = ct * 2;
    int r0 = blockIdx.x * 2;
    __shared__ float scf[2][CC];
    for (int i = t; i < 2*CC; i += 128)
        scf[i >> 7][i & 127] = g_acc.cf[(r0 + (i >> 7))*CC + (i & 127)];
    __syncthreads();
    float2 b = *(const float2*)&cb1[c0];
    float a0 = b.x, a1 = b.y;
    #pragma unroll 8
    for (int k = 0; k < CC; k++) {
        float2 w = *(const float2*)&cw1[k*CC + c0];
        float x = scf[r][k];
        a0 = fmaf(x, w.x, a0); a1 = fmaf(x, w.y, a1);
    }
    float2 res; res.x = a0; res.y = a1;
    *(float2*)&g_hid[(r0+r)*CC + c0] = res;
    atomicAdd(&g_acc.s1[c0],   a0);     atomicAdd(&g_acc.s1[c0+1], a1);
    atomicAdd(&g_acc.s2[c0],   a0*a0);  atomicAdd(&g_acc.s2[c0+1], a1*a1);
}

// ================= BN+ReLU + gemm2 + K or V projection =====================
// grid 128: (rowgroup 0..63) x (half: 0=K, 1=V). block 128: 4 rows x 32 colthreads
__global__ void k_gemm2kv(const float* __restrict__ cw2, const float* __restrict__ cb2,
                          const float* __restrict__ cg1, const float* __restrict__ cbe1,
                          const float* __restrict__ wk,  const float* __restrict__ bk,
                          const float* __restrict__ wv,  const float* __restrict__ bv) {
    int t = threadIdx.x;
    int half = blockIdx.x & 1;
    int r0 = (blockIdx.x >> 1) * 4;
    __shared__ float act[4][CC], hrow[4][CC];
    float mu  = g_acc.s1[t] * (1.f/NSV);
    float var = g_acc.s2[t] * (1.f/NSV) - mu * mu;
    float A = cg1[t] * rsqrtf(var + EPSF);
    float D = cbe1[t] - mu * A;
    #pragma unroll
    for (int rr = 0; rr < 4; rr++)
        act[rr][t] = fmaxf(fmaf(g_hid[(r0+rr)*CC + t], A, D), 0.f);
    __syncthreads();
    int r = t >> 5, ct = t & 31, c0 = ct * 4;
    {
        float4 acc = *(const float4*)&cb2[c0];
        #pragma unroll 4
        for (int k = 0; k < CC; k++) {
            float4 w = *(const float4*)&cw2[k*CC + c0];
            float x = act[r][k];
            acc.x = fmaf(x, w.x, acc.x); acc.y = fmaf(x, w.y, acc.y);
            acc.z = fmaf(x, w.z, acc.z); acc.w = fmaf(x, w.w, acc.w);
        }
        *(float4*)&hrow[r][c0] = acc;
    }
    __syncthreads();
    {
        const float* W = half ? wv : wk;
        const float* B = half ? bv : bk;
        float4 acc = *(const float4*)&B[c0];
        #pragma unroll 4
        for (int k = 0; k < CC; k++) {
            float4 w = *(const float4*)&W[k*CC + c0];
            float x = hrow[r][k];
            acc.x = fmaf(x, w.x, acc.x); acc.y = fmaf(x, w.y, acc.y);
            acc.z = fmaf(x, w.z, acc.z); acc.w = fmaf(x, w.w, acc.w);
        }
        float* dst = half ? g_vT : g_kT;
        dst[(c0+0)*NSV + r0 + r] = acc.x;
        dst[(c0+1)*NSV + r0 + r] = acc.y;
        dst[(c0+2)*NSV + r0 + r] = acc.z;
        dst[(c0+3)*NSV + r0 + r] = acc.w;
    }
}

// ================= fully fused attention (packed f32x2) ====================
__global__ void __launch_bounds__(256, 2)
k_attn(const int* __restrict__ idx, const float* __restrict__ feat,
       const float* __restrict__ wq, const float* __restrict__ bq,
       const float* __restrict__ wo, const float* __restrict__ bo,
       const float* __restrict__ lng, const float* __restrict__ lnb,
       const float* __restrict__ pw2, const float* __restrict__ pb2) {
    extern __shared__ float sm[];
    float* sfeatT = sm;                    // [k][g]   1024
    float* sqT    = sfeatT + CC*GQ;        // [c][g]   1024
    float* satt   = sqT + CC*GQ;           // [h][s][g] 16384
    float* sctxT  = satt + NH*NSV*GQ;      // [k][g]   1024
    float* st     = sctxT + CC*GQ;         // [j][g]   512
    float* sw     = st + 64*GQ;            // 256
    float* spw2   = sw + 256;              // 64
    float* sred   = spw2 + 64;             // 64
    float* spos   = sred + 64;             // 24

    int t = threadIdx.x;
    int n0 = blockIdx.x * GQ;
    int c = t & (CC-1), grp = t >> 7, g0 = grp * 4;

    sw[t] = g_pweff[t];
    if (t < 64) spw2[t] = pw2[t];
    if (t < GQ*3) spos[t] = (float)idx[(n0 + t/3)*4 + 1 + (t%3)];
    #pragma unroll
    for (int i = 0; i < GQ*CC/256; i++) {
        int li = t + 256*i;
        sfeatT[(li & (CC-1))*GQ + (li >> 7)] = feat[n0*CC + li];
    }
    __syncthreads();

    for (int p = t; p < 64*GQ; p += 256) {
        int j = p >> 3, g = p & 7;
        st[p] = fmaf(spos[g*3], sw[j],
                fmaf(spos[g*3+1], sw[64+j],
                fmaf(spos[g*3+2], sw[128+j], sw[192+j])));
    }

    // ---- q projection ----
    {
        float b = bq[c];
        ull a0 = pk(b, b), a1 = pk(b, b);
        #pragma unroll 4
        for (int k = 0; k < CC; k++) {
            float w = wq[k*CC + c];
            ull w2 = pk(w, w);
            FMA2(a0, pk2(*(const float2*)&sfeatT[k*GQ + g0]),     w2, a0);
            FMA2(a1, pk2(*(const float2*)&sfeatT[k*GQ + g0 + 2]), w2, a1);
        }
        float q0,q1,q2,q3;
        upk(q0,q1,a0); upk(q2,q3,a1);
        sqT[c*GQ + g0+0] = q0*0.25f; sqT[c*GQ + g0+1] = q1*0.25f;
        sqT[c*GQ + g0+2] = q2*0.25f; sqT[c*GQ + g0+3] = q3*0.25f;
    }
    __syncthreads();

    // ---- pbias (factorized, BN folded): thread = super-voxel s ----
    float pb[GQ];
    {
        int4 u = g_unq[t];
        float ux = (float)u.y, uy = (float)u.z, uz = (float)u.w;
        float pbv = pb2[0];
        #pragma unroll
        for (int g = 0; g < GQ; g++) pb[g] = pbv;
        #pragma unroll 2
        for (int j = 0; j < 64; j++) {
            float uj = fmaf(ux, sw[j], fmaf(uy, sw[64+j], uz * sw[128+j]));
            float w2j = spw2[j];
            float4 tA = *(const float4*)&st[j*GQ];
            float4 tB = *(const float4*)&st[j*GQ + 4];
            pb[0] = fmaf(fmaxf(tA.x - uj, 0.f), w2j, pb[0]);
            pb[1] = fmaf(fmaxf(tA.y - uj, 0.f), w2j, pb[1]);
            pb[2] = fmaf(fmaxf(tA.z - uj, 0.f), w2j, pb[2]);
            pb[3] = fmaf(fmaxf(tA.w - uj, 0.f), w2j, pb[3]);
            pb[4] = fmaf(fmaxf(tB.x - uj, 0.f), w2j, pb[4]);
            pb[5] = fmaf(fmaxf(tB.y - uj, 0.f), w2j, pb[5]);
            pb[6] = fmaf(fmaxf(tB.z - uj, 0.f), w2j, pb[6]);
            pb[7] = fmaf(fmaxf(tB.w - uj, 0.f), w2j, pb[7]);
        }
    }
    // ---- scores per head ----
    {
        ull pbp0 = pk(pb[0],pb[1]), pbp1 = pk(pb[2],pb[3]);
        ull pbp2 = pk(pb[4],pb[5]), pbp3 = pk(pb[6],pb[7]);
        for (int h = 0; h < NH; h++) {
            ull a0 = pbp0, a1 = pbp1, a2 = pbp2, a3 = pbp3;
            #pragma unroll
            for (int c16 = 0; c16 < DHD; c16++) {
                int cc = h*DHD + c16;
                float kv = g_kT[cc*NSV + t];
                ull kv2 = pk(kv, kv);
                FMA2(a0, pk2(*(const float2*)&sqT[cc*GQ + 0]), kv2, a0);
                FMA2(a1, pk2(*(const float2*)&sqT[cc*GQ + 2]), kv2, a1);
                FMA2(a2, pk2(*(const float2*)&sqT[cc*GQ + 4]), kv2, a2);
                FMA2(a3, pk2(*(const float2*)&sqT[cc*GQ + 6]), kv2, a3);
            }
            ull* dst = (ull*)&satt[(h*NSV + t)*GQ];
            dst[0] = a0; dst[1] = a1; dst[2] = a2; dst[3] = a3;
        }
    }
    __syncthreads();

    // ---- softmax over s for each (h,g) ----
    {
        int warp = t >> 5, lane = t & 31;
        for (int p = warp; p < GQ*NH; p += 8) {
            int h = p >> 3, g = p & 7;
            float* row = satt + h*NSV*GQ + g;
            float vals[8];
            float m = -1e30f;
            #pragma unroll
            for (int k = 0; k < 8; k++) { vals[k] = row[(lane + 32*k)*GQ]; m = fmaxf(m, vals[k]); }
            for (int o = 16; o; o >>= 1) m = fmaxf(m, __shfl_xor_sync(~0u, m, o));
            float sum = 0.f;
            #pragma unroll
            for (int k = 0; k < 8; k++) { vals[k] = __expf(vals[k] - m); sum += vals[k]; }
            for (int o = 16; o; o >>= 1) sum += __shfl_xor_sync(~0u, sum, o);
            float inv = 1.f / sum;
            #pragma unroll
            for (int k = 0; k < 8; k++) row[(lane + 32*k)*GQ] = vals[k] * inv;
        }
    }
    __syncthreads();

    // ---- attn @ V (V transposed: contiguous float4 along s) ----
    {
        int hh = c >> 4;
        ull a0 = 0ull, a1 = 0ull;
        const float4* vrow = (const float4*)&g_vT[c*NSV];
        const float* abase = satt + hh*NSV*GQ + g0;
        #pragma unroll 4
        for (int s4 = 0; s4 < NSV/4; s4++) {
            float4 vv = vrow[s4];
            int s = s4 * 4;
            FMA2(a0, pk2(*(const float2*)&abase[(s+0)*GQ]),     pk(vv.x, vv.x), a0);
            FMA2(a1, pk2(*(const float2*)&abase[(s+0)*GQ + 2]), pk(vv.x, vv.x), a1);
            FMA2(a0, pk2(*(const float2*)&abase[(s+1)*GQ]),     pk(vv.y, vv.y), a0);
            FMA2(a1, pk2(*(const float2*)&abase[(s+1)*GQ + 2]), pk(vv.y, vv.y), a1);
            FMA2(a0, pk2(*(const float2*)&abase[(s+2)*GQ]),     pk(vv.z, vv.z), a0);
            FMA2(a1, pk2(*(const float2*)&abase[(s+2)*GQ + 2]), pk(vv.z, vv.z), a1);
            FMA2(a0, pk2(*(const float2*)&abase[(s+3)*GQ]),     pk(vv.w, vv.w), a0);
            FMA2(a1, pk2(*(const float2*)&abase[(s+3)*GQ + 2]), pk(vv.w, vv.w), a1);
        }
        float x0,x1,x2,x3;
        upk(x0,x1,a0); upk(x2,x3,a1);
        sctxT[c*GQ + g0+0] = x0; sctxT[c*GQ + g0+1] = x1;
        sctxT[c*GQ + g0+2] = x2; sctxT[c*GQ + g0+3] = x3;
    }
    __syncthreads();

    // ---- o-proj + residual + LayerNorm ----
    {
        float b = bo[c];
        ull a0 = pk(b, b), a1 = pk(b, b);
        #pragma unroll 4
        for (int k = 0; k < CC; k++) {
            float w = wo[k*CC + c];
            ull w2 = pk(w, w);
            FMA2(a0, pk2(*(const float2*)&sctxT[k*GQ + g0]),     w2, a0);
            FMA2(a1, pk2(*(const float2*)&sctxT[k*GQ + g0 + 2]), w2, a1);
        }
        float o0,o1,o2,o3;
        upk(o0,o1,a0); upk(o2,o3,a1);
        float yv[4];
        yv[0] = sfeatT[c*GQ + g0+0] + o0;
        yv[1] = sfeatT[c*GQ + g0+1] + o1;
        yv[2] = sfeatT[c*GQ + g0+2] + o2;
        yv[3] = sfeatT[c*GQ + g0+3] + o3;

        int warp = t >> 5, lane = t & 31, w4 = warp & 3;
        #pragma unroll
        for (int gg = 0; gg < 4; gg++) {
            float s = yv[gg], ss = yv[gg]*yv[gg];
            for (int o = 16; o; o >>= 1) {
                s  += __shfl_xor_sync(~0u, s, o);
                ss += __shfl_xor_sync(~0u, ss, o);
            }
            if (lane == 0) {
                sred[(g0+gg)*4 + w4]      = s;
                sred[32 + (g0+gg)*4 + w4] = ss;
            }
        }
        __syncthreads();
        float lg = lng[c], lb = lnb[c];
        #pragma unroll
        for (int gg = 0; gg < 4; gg++) {
            int g = g0 + gg;
            float s  = sred[g*4+0] + sred[g*4+1] + sred[g*4+2] + sred[g*4+3];
            float ss = sred[32+g*4+0] + sred[32+g*4+1] + sred[32+g*4+2] + sred[32+g*4+3];
            float mu = s * (1.f/CC), var = ss * (1.f/CC) - mu*mu;
            g_y[(n0+g)*CC + c] = (yv[gg] - mu) * rsqrtf(var + EPSF) * lg + lb;
        }
    }
}

// ================= submanifold 3^3 conv (cp.async double-buffered) =========
__global__ void __launch_bounds__(320, 2)
k_conv(const int* __restrict__ idx, const float* __restrict__ segw,
       const float* __restrict__ segb, float* __restrict__ out) {
    __shared__ float sW[2][CC*NCL];   // 2 x 10 KB
    __shared__ int4 svox[32];
    int t = threadIdx.x;
    int n0 = blockIdx.x * 32;
    if (t < 32) svox[t] = ((const int4*)idx)[n0 + t];

    // stage slice 0 into buffer 0
    {
        unsigned dst = smem_u32(&sW[0][t*4]);
        CPA16(dst, &segw[t*4]);
        CPA16(dst + 1280*4, &segw[1280 + t*4]);
        CPA_COMMIT();
    }

    int v = t / 10, op = t - v * 10;     // 32 voxels x 10 oc-pairs
    int4 pv = svox[0];                    // placeholder, fixed after sync
    float2 bb = *(const float2*)&segb[op*2];
    ull acc0 = pk(bb.x, bb.y), acc1 = 0ull;

    for (int d = 0; d < 27; d++) {
        if (d < 26) {
            int buf = (d + 1) & 1;
            unsigned dst = smem_u32(&sW[buf][t*4]);
            const float* src = &segw[(d+1)*CC*NCL + t*4];
            CPA16(dst, src);
            CPA16(dst + 1280*4, src + 1280);
            CPA_COMMIT();
            CPA_WAIT(1);
        } else {
            CPA_WAIT(0);
        }
        __syncthreads();
        if (d == 0) pv = svox[v];
        const float* wbuf = sW[d & 1];
        int ax = d / 9, ay = (d / 3) % 3, az = d % 3;
        int x = pv.y + ax - 1, y = pv.z + ay - 1, z = pv.w + az - 1;
        if (x >= 0 && x < GXD && y >= 0 && y < GYD && z >= 0 && z < GZD) {
            int m = g_map[((pv.x * GXD + x) * GYD + y) * GZD + z];
            if (m > 0) {
                const float* yr = &g_y[(m-1)*CC];
                #pragma unroll 8
                for (int c2 = 0; c2 < CC; c2 += 2) {
                    float y0 = yr[c2], y1 = yr[c2+1];
                    FMA2(acc0, pk(y0, y0), pk2(*(const float2*)&wbuf[c2*NCL + op*2]),     acc0);
                    FMA2(acc1, pk(y1, y1), pk2(*(const float2*)&wbuf[(c2+1)*NCL + op*2]), acc1);
                }
            }
        }
        __syncthreads();
    }
    float a0, a1, b0, b1;
    upk(a0, a1, acc0); upk(b0, b1, acc1);
    float2 res; res.x = a0 + b0; res.y = a1 + b1;
    *(float2*)&out[(n0 + v)*NCL + op*2] = res;
}

// --------------------------------------------------------------------------
extern "C" void kernel_launch(void* const* d_in, const int* in_sizes, int n_in,
                              void* d_out, int out_size) {
    const int*   idx  = (const int*)  d_in[0];
    const float* feat = (const float*)d_in[1];
    const float* cw1  = (const float*)d_in[2];
    const float* cb1  = (const float*)d_in[3];
    const float* cg1  = (const float*)d_in[4];
    const float* cbe1 = (const float*)d_in[5];
    const float* cw2  = (const float*)d_in[6];
    const float* cb2  = (const float*)d_in[7];
    const float* pw1  = (const float*)d_in[8];
    const float* pb1  = (const float*)d_in[9];
    const float* pg1  = (const float*)d_in[10];
    const float* pbe1 = (const float*)d_in[11];
    const float* pw2  = (const float*)d_in[12];
    const float* pb2  = (const float*)d_in[13];
    const float* wq   = (const float*)d_in[14];
    const float* bq   = (const float*)d_in[15];
    const float* wk   = (const float*)d_in[16];
    const float* bk   = (const float*)d_in[17];
    const float* wv   = (const float*)d_in[18];
    const float* bv   = (const float*)d_in[19];
    const float* wo   = (const float*)d_in[20];
    const float* bo   = (const float*)d_in[21];
    const float* ln_g = (const float*)d_in[22];
    const float* ln_b = (const float*)d_in[23];
    const float* segw = (const float*)d_in[24];
    const float* segb = (const float*)d_in[25];

    void* p_acc;
    cudaGetSymbolAddress(&p_acc, g_acc);

    constexpr int ATTN_SMEM = (CC*GQ*3 + NH*NSV*GQ + 64*GQ + 256 + 64 + 64 + 24 + 8) * 4;
    cudaFuncSetAttribute(k_attn, cudaFuncAttributeMaxDynamicSharedMemorySize, ATTN_SMEM);

    cudaMemsetAsync(p_acc, 0, sizeof(Acc), 0);

    k_prep    <<<1, 256>>>(idx, pw1, pb1, pg1, pbe1);
    k_sms     <<<NV/4, 128>>>(feat);
    k_gemm1   <<<NSV/2, 128>>>(cw1, cb1);
    k_gemm2kv <<<NSV/2, 128>>>(cw2, cb2, cg1, cbe1, wk, bk, wv, bv);
    k_attn    <<<NV/GQ, 256, ATTN_SMEM>>>(idx, feat, wq, bq, wo, bo, ln_g, ln_b, pw2, pb2);
    k_conv    <<<NV/32, 320>>>(idx, segw, segb, (float*)d_out);
}

// round 5
// speedup vs baseline: 1.0404x; 1.0404x over previous
#include <cuda_runtime.h>

#define NV   4096
#define NSV  256
#define BB   2
#define GXD  128
#define GYD  128
#define GZD  16
#define CC   128
#define NCL  20
#define NH   8
#define DHD  16
#define MAPSZ (BB*GXD*GYD*GZD)
#define EPSF 1e-5f
#define GQ   8

// ---------------- packed f32x2 helpers ----------------
typedef unsigned long long ull;
__device__ __forceinline__ ull pk(float lo, float hi) {
    ull r; asm("mov.b64 %0, {%1,%2};" : "=l"(r) : "f"(lo), "f"(hi)); return r;
}
__device__ __forceinline__ ull pk2(float2 f) { return pk(f.x, f.y); }
__device__ __forceinline__ void upk(float& lo, float& hi, ull v) {
    asm("mov.b64 {%0,%1}, %2;" : "=f"(lo), "=f"(hi) : "l"(v));
}
#define FMA2(d,a,b,c) asm("fma.rn.f32x2 %0, %1, %2, %3;" : "=l"(d) : "l"(a), "l"(b), "l"(c))

// ---------------- device scratch ----------------
struct Acc { float s1[CC]; float s2[CC]; };
__device__ Acc  g_acc;
__device__ int4 g_unq[NSV];
__device__ int  g_members[NSV*16];
__device__ float g_hid[NSV*CC];
__device__ float g_kT[CC*NSV];
__device__ float g_vT[CC*NSV];
__device__ float g_y[NV*CC];
__device__ int   g_map[MAPSZ];          // zero-init; stores n+1 (idempotent per input)
__device__ float g_pweff[4*64];

// ================= k_prep: keys, unique, members, pbias BN fold ===========
__global__ void k_prep(const int* __restrict__ idx,
                       const float* __restrict__ pw1, const float* __restrict__ pb1,
                       const float* __restrict__ pg1, const float* __restrict__ pbe1) {
    __shared__ unsigned sflags[256];
    __shared__ unsigned short skeys[NV];
    __shared__ int sscan[256], srank[256], scnt[256];
    __shared__ long long wred[8];
    __shared__ double Si[9], Su[9], md[3], Cv[3][3];
    int t = threadIdx.x, lane = t & 31, wid = t >> 5;

    sflags[t] = 0u;
    scnt[t] = 0;
    __syncthreads();

    long long m[9] = {0,0,0,0,0,0,0,0,0};
    for (int i = t; i < NV; i += 256) {
        int4 p = ((const int4*)idx)[i];
        int key = ((p.x * 32 + (p.y >> 2)) * 32 + (p.z >> 2)) * 4 + (p.w >> 2);
        skeys[i] = (unsigned short)key;
        atomicOr(&sflags[key >> 5], 1u << (key & 31));
        g_map[((p.x * GXD + p.y) * GYD + p.z) * GZD + p.w] = i + 1;
        long long xs = p.y, ys = p.z, zs = p.w;
        m[0]+=xs; m[1]+=ys; m[2]+=zs; m[3]+=xs*xs; m[4]+=ys*ys; m[5]+=zs*zs;
        m[6]+=xs*ys; m[7]+=xs*zs; m[8]+=ys*zs;
    }
    __syncthreads();

    unsigned w = sflags[t];
    int cnt = __popc(w);
    sscan[t] = cnt; __syncthreads();
    for (int off = 1; off < 256; off <<= 1) {
        int v = (t >= off) ? sscan[t - off] : 0;
        __syncthreads(); sscan[t] += v; __syncthreads();
    }
    int excl = sscan[t] - cnt;
    srank[t] = excl;
    unsigned wb = w;
    while (wb) {
        int bit = __ffs(wb) - 1; wb &= wb - 1;
        int rank = excl + __popc(w & ((1u << bit) - 1u));
        int key = t * 32 + bit;
        int4 u;
        u.w = key & 3; u.z = (key >> 2) & 31; u.y = (key >> 7) & 31; u.x = key >> 12;
        g_unq[rank] = u;
    }
    __syncthreads();

    // member lists: 16 voxels per supervoxel
    for (int i = t; i < NV; i += 256) {
        int key = skeys[i];
        int s = srank[key >> 5] + __popc(sflags[key >> 5] & ((1u << (key & 31)) - 1u));
        int slot = atomicAdd(&scnt[s], 1);
        g_members[s*16 + slot] = i;
    }

    for (int k = 0; k < 9; k++) {
        long long v = m[k];
        for (int o = 16; o; o >>= 1) v += __shfl_xor_sync(~0u, v, o);
        if (lane == 0) wred[wid] = v;
        __syncthreads();
        if (t == 0) { long long s = 0; for (int i = 0; i < 8; i++) s += wred[i]; Si[k] = (double)s; }
        __syncthreads();
    }
    {
        int4 u = g_unq[t];
        long long xs = u.y, ys = u.z, zs = u.w;
        long long mu9[9] = { xs, ys, zs, xs*xs, ys*ys, zs*zs, xs*ys, xs*zs, ys*zs };
        for (int k = 0; k < 9; k++) {
            long long v = mu9[k];
            for (int o = 16; o; o >>= 1) v += __shfl_xor_sync(~0u, v, o);
            if (lane == 0) wred[wid] = v;
            __syncthreads();
            if (t == 0) { long long s = 0; for (int i = 0; i < 8; i++) s += wred[i]; Su[k] = (double)s; }
            __syncthreads();
        }
    }
    if (t == 0) {
        double mi[3], mu_[3];
        for (int a = 0; a < 3; a++) {
            mi[a]  = Si[a] / (double)NV;
            mu_[a] = Su[a] / (double)NSV;
            md[a]  = mi[a] - mu_[a];
        }
        const int pid[3][3] = { {3,6,7}, {6,4,8}, {7,8,5} };
        for (int a = 0; a < 3; a++)
            for (int b = 0; b < 3; b++)
                Cv[a][b] = (Si[pid[a][b]] / (double)NV  - mi[a]  * mi[b])
                         + (Su[pid[a][b]] / (double)NSV - mu_[a] * mu_[b]);
    }
    __syncthreads();
    if (t < 64) {
        int j = t;
        double w3[3];
        for (int a = 0; a < 3; a++) w3[a] = (double)pw1[a*64 + j];
        double mu = md[0]*w3[0] + md[1]*w3[1] + md[2]*w3[2] + (double)pb1[j];
        double var = 0.0;
        for (int a = 0; a < 3; a++)
            for (int b = 0; b < 3; b++)
                var += w3[a] * Cv[a][b] * w3[b];
        float s = rsqrtf((float)var + EPSF) * pg1[j];
        for (int a = 0; a < 3; a++) g_pweff[a*64 + j] = (float)w3[a] * s;
        g_pweff[192 + j] = (float)((double)pb1[j] - mu) * s + pbe1[j];
    }
}

// ================= fused softmax-scatter + gemm1 + BN stats ================
// block = one supervoxel, 512 threads
__global__ void __launch_bounds__(512, 2)
k_sgemm1(const float* __restrict__ feat,
         const float* __restrict__ cw1, const float* __restrict__ cb1) {
    __shared__ float sft[16][CC];
    __shared__ float cfr[CC];
    __shared__ float pred[4][CC];
    int t = threadIdx.x, s = blockIdx.x;
    int wrp = t >> 5, lane = t & 31;

    // phase A: softmax of the 16 member rows (one warp per row)
    {
        int row = g_members[s*16 + wrp];
        float4 v = *(const float4*)&feat[row*CC + lane*4];
        float m = fmaxf(fmaxf(v.x, v.y), fmaxf(v.z, v.w));
        for (int o = 16; o; o >>= 1) m = fmaxf(m, __shfl_xor_sync(~0u, m, o));
        float e0 = __expf(v.x - m), e1 = __expf(v.y - m);
        float e2 = __expf(v.z - m), e3 = __expf(v.w - m);
        float sum = e0 + e1 + e2 + e3;
        for (int o = 16; o; o >>= 1) sum += __shfl_xor_sync(~0u, sum, o);
        float inv = 1.f / sum;
        float4 r; r.x = e0*inv; r.y = e1*inv; r.z = e2*inv; r.w = e3*inv;
        *(float4*)&sft[wrp][lane*4] = r;
    }
    __syncthreads();
    // phase B: cf row
    if (t < CC) {
        float a = 0.f;
        #pragma unroll
        for (int r = 0; r < 16; r++) a += sft[r][t];
        cfr[t] = a;
    }
    __syncthreads();
    // phase C: gemm row, 4-way k-split
    {
        int c = t & (CC-1), ks = t >> 7;
        float acc = 0.f;
        int k0 = ks * 32;
        #pragma unroll 8
        for (int k = k0; k < k0 + 32; k++)
            acc = fmaf(cfr[k], cw1[k*CC + c], acc);
        pred[ks][c] = acc;
    }
    __syncthreads();
    if (t < CC) {
        float v = pred[0][t] + pred[1][t] + pred[2][t] + pred[3][t] + cb1[t];
        g_hid[s*CC + t] = v;
        atomicAdd(&g_acc.s1[t], v);
        atomicAdd(&g_acc.s2[t], v*v);
    }
}

// ================= BN+ReLU + gemm2 + K,V projections (k-split) =============
// block = one supervoxel row, 512 threads
__global__ void __launch_bounds__(512, 2)
k_gemm2kv(const float* __restrict__ cw2, const float* __restrict__ cb2,
          const float* __restrict__ cg1, const float* __restrict__ cbe1,
          const float* __restrict__ wk,  const float* __restrict__ bk,
          const float* __restrict__ wv,  const float* __restrict__ bv) {
    __shared__ float act[CC], hrow[CC];
    __shared__ float pr[4][CC];
    int t = threadIdx.x, r = blockIdx.x;

    if (t < CC) {
        float mu  = g_acc.s1[t] * (1.f/NSV);
        float var = g_acc.s2[t] * (1.f/NSV) - mu * mu;
        float A = cg1[t] * rsqrtf(var + EPSF);
        float D = cbe1[t] - mu * A;
        act[t] = fmaxf(fmaf(g_hid[r*CC + t], A, D), 0.f);
    }
    __syncthreads();
    // gemm2: 4-way k-split
    {
        int c = t & (CC-1), ks = t >> 7;
        float acc = 0.f;
        int k0 = ks * 32;
        #pragma unroll 8
        for (int k = k0; k < k0 + 32; k++)
            acc = fmaf(act[k], cw2[k*CC + c], acc);
        pr[ks][c] = acc;
    }
    __syncthreads();
    if (t < CC) hrow[t] = pr[0][t] + pr[1][t] + pr[2][t] + pr[3][t] + cb2[t];
    __syncthreads();
    // K and V in parallel: sel = (proj, ks2)
    {
        int c = t & (CC-1), sel = t >> 7;         // 0,1 = K halves; 2,3 = V halves
        const float* W = (sel < 2) ? wk : wv;
        int k0 = (sel & 1) * 64;
        float acc = 0.f;
        #pragma unroll 8
        for (int k = k0; k < k0 + 64; k++)
            acc = fmaf(hrow[k], W[k*CC + c], acc);
        pr[sel][c] = acc;
    }
    __syncthreads();
    if (t < 2*CC) {
        int c = t & (CC-1), proj = t >> 7;
        float val = pr[proj*2][c] + pr[proj*2+1][c] + (proj ? bv[c] : bk[c]);
        (proj ? g_vT : g_kT)[c*NSV + r] = val;
    }
}

// ================= fully fused attention (packed f32x2) ====================
__global__ void __launch_bounds__(256, 2)
k_attn(const int* __restrict__ idx, const float* __restrict__ feat,
       const float* __restrict__ wq, const float* __restrict__ bq,
       const float* __restrict__ wo, const float* __restrict__ bo,
       const float* __restrict__ lng, const float* __restrict__ lnb,
       const float* __restrict__ pw2, const float* __restrict__ pb2) {
    extern __shared__ float sm[];
    float* sfeatT = sm;                    // [k][g]   1024
    float* sqT    = sfeatT + CC*GQ;        // [c][g]   1024
    float* satt   = sqT + CC*GQ;           // [h][s][g] 16384
    float* sctxT  = satt + NH*NSV*GQ;      // [k][g]   1024
    float* st     = sctxT + CC*GQ;         // [j][g]   512
    float* sw     = st + 64*GQ;            // 256
    float* spw2   = sw + 256;              // 64
    float* sred   = spw2 + 64;             // 64
    float* spos   = sred + 64;             // 24

    int t = threadIdx.x;
    int n0 = blockIdx.x * GQ;
    int c = t & (CC-1), grp = t >> 7, g0 = grp * 4;

    sw[t] = g_pweff[t];
    if (t < 64) spw2[t] = pw2[t];
    if (t < GQ*3) spos[t] = (float)idx[(n0 + t/3)*4 + 1 + (t%3)];
    #pragma unroll
    for (int i = 0; i < GQ*CC/256; i++) {
        int li = t + 256*i;
        sfeatT[(li & (CC-1))*GQ + (li >> 7)] = feat[n0*CC + li];
    }
    __syncthreads();

    for (int p = t; p < 64*GQ; p += 256) {
        int j = p >> 3, g = p & 7;
        st[p] = fmaf(spos[g*3], sw[j],
                fmaf(spos[g*3+1], sw[64+j],
                fmaf(spos[g*3+2], sw[128+j], sw[192+j])));
    }

    // ---- q projection ----
    {
        float b = bq[c];
        ull a0 = pk(b, b), a1 = pk(b, b);
        #pragma unroll 4
        for (int k = 0; k < CC; k++) {
            float w = wq[k*CC + c];
            ull w2 = pk(w, w);
            FMA2(a0, pk2(*(const float2*)&sfeatT[k*GQ + g0]),     w2, a0);
            FMA2(a1, pk2(*(const float2*)&sfeatT[k*GQ + g0 + 2]), w2, a1);
        }
        float q0,q1,q2,q3;
        upk(q0,q1,a0); upk(q2,q3,a1);
        sqT[c*GQ + g0+0] = q0*0.25f; sqT[c*GQ + g0+1] = q1*0.25f;
        sqT[c*GQ + g0+2] = q2*0.25f; sqT[c*GQ + g0+3] = q3*0.25f;
    }
    __syncthreads();

    // ---- pbias (factorized, BN folded): thread = super-voxel s ----
    float pb[GQ];
    {
        int4 u = g_unq[t];
        float ux = (float)u.y, uy = (float)u.z, uz = (float)u.w;
        float pbv = pb2[0];
        #pragma unroll
        for (int g = 0; g < GQ; g++) pb[g] = pbv;
        #pragma unroll 2
        for (int j = 0; j < 64; j++) {
            float uj = fmaf(ux, sw[j], fmaf(uy, sw[64+j], uz * sw[128+j]));
            float w2j = spw2[j];
            float4 tA = *(const float4*)&st[j*GQ];
            float4 tB = *(const float4*)&st[j*GQ + 4];
            pb[0] = fmaf(fmaxf(tA.x - uj, 0.f), w2j, pb[0]);
            pb[1] = fmaf(fmaxf(tA.y - uj, 0.f), w2j, pb[1]);
            pb[2] = fmaf(fmaxf(tA.z - uj, 0.f), w2j, pb[2]);
            pb[3] = fmaf(fmaxf(tA.w - uj, 0.f), w2j, pb[3]);
            pb[4] = fmaf(fmaxf(tB.x - uj, 0.f), w2j, pb[4]);
            pb[5] = fmaf(fmaxf(tB.y - uj, 0.f), w2j, pb[5]);
            pb[6] = fmaf(fmaxf(tB.z - uj, 0.f), w2j, pb[6]);
            pb[7] = fmaf(fmaxf(tB.w - uj, 0.f), w2j, pb[7]);
        }
    }
    // ---- scores per head ----
    {
        ull pbp0 = pk(pb[0],pb[1]), pbp1 = pk(pb[2],pb[3]);
        ull pbp2 = pk(pb[4],pb[5]), pbp3 = pk(pb[6],pb[7]);
        for (int h = 0; h < NH; h++) {
            ull a0 = pbp0, a1 = pbp1, a2 = pbp2, a3 = pbp3;
            #pragma unroll
            for (int c16 = 0; c16 < DHD; c16++) {
                int cc = h*DHD + c16;
                float kv = g_kT[cc*NSV + t];
                ull kv2 = pk(kv, kv);
                FMA2(a0, pk2(*(const float2*)&sqT[cc*GQ + 0]), kv2, a0);
                FMA2(a1, pk2(*(const float2*)&sqT[cc*GQ + 2]), kv2, a1);
                FMA2(a2, pk2(*(const float2*)&sqT[cc*GQ + 4]), kv2, a2);
                FMA2(a3, pk2(*(const float2*)&sqT[cc*GQ + 6]), kv2, a3);
            }
            ull* dst = (ull*)&satt[(h*NSV + t)*GQ];
            dst[0] = a0; dst[1] = a1; dst[2] = a2; dst[3] = a3;
        }
    }
    __syncthreads();

    // ---- softmax over s for each (h,g) ----
    {
        int warp = t >> 5, lane = t & 31;
        for (int p = warp; p < GQ*NH; p += 8) {
            int h = p >> 3, g = p & 7;
            float* row = satt + h*NSV*GQ + g;
            float vals[8];
            float m = -1e30f;
            #pragma unroll
            for (int k = 0; k < 8; k++) { vals[k] = row[(lane + 32*k)*GQ]; m = fmaxf(m, vals[k]); }
            for (int o = 16; o; o >>= 1) m = fmaxf(m, __shfl_xor_sync(~0u, m, o));
            float sum = 0.f;
            #pragma unroll
            for (int k = 0; k < 8; k++) { vals[k] = __expf(vals[k] - m); sum += vals[k]; }
            for (int o = 16; o; o >>= 1) sum += __shfl_xor_sync(~0u, sum, o);
            float inv = 1.f / sum;
            #pragma unroll
            for (int k = 0; k < 8; k++) row[(lane + 32*k)*GQ] = vals[k] * inv;
        }
    }
    __syncthreads();

    // ---- attn @ V (V transposed: contiguous float4 along s) ----
    {
        int hh = c >> 4;
        ull a0 = 0ull, a1 = 0ull;
        const float4* vrow = (const float4*)&g_vT[c*NSV];
        const float* abase = satt + hh*NSV*GQ + g0;
        #pragma unroll 4
        for (int s4 = 0; s4 < NSV/4; s4++) {
            float4 vv = vrow[s4];
            int s = s4 * 4;
            FMA2(a0, pk2(*(const float2*)&abase[(s+0)*GQ]),     pk(vv.x, vv.x), a0);
            FMA2(a1, pk2(*(const float2*)&abase[(s+0)*GQ + 2]), pk(vv.x, vv.x), a1);
            FMA2(a0, pk2(*(const float2*)&abase[(s+1)*GQ]),     pk(vv.y, vv.y), a0);
            FMA2(a1, pk2(*(const float2*)&abase[(s+1)*GQ + 2]), pk(vv.y, vv.y), a1);
            FMA2(a0, pk2(*(const float2*)&abase[(s+2)*GQ]),     pk(vv.z, vv.z), a0);
            FMA2(a1, pk2(*(const float2*)&abase[(s+2)*GQ + 2]), pk(vv.z, vv.z), a1);
            FMA2(a0, pk2(*(const float2*)&abase[(s+3)*GQ]),     pk(vv.w, vv.w), a0);
            FMA2(a1, pk2(*(const float2*)&abase[(s+3)*GQ + 2]), pk(vv.w, vv.w), a1);
        }
        float x0,x1,x2,x3;
        upk(x0,x1,a0); upk(x2,x3,a1);
        sctxT[c*GQ + g0+0] = x0; sctxT[c*GQ + g0+1] = x1;
        sctxT[c*GQ + g0+2] = x2; sctxT[c*GQ + g0+3] = x3;
    }
    __syncthreads();

    // ---- o-proj + residual + LayerNorm ----
    {
        float b = bo[c];
        ull a0 = pk(b, b), a1 = pk(b, b);
        #pragma unroll 4
        for (int k = 0; k < CC; k++) {
            float w = wo[k*CC + c];
            ull w2 = pk(w, w);
            FMA2(a0, pk2(*(const float2*)&sctxT[k*GQ + g0]),     w2, a0);
            FMA2(a1, pk2(*(const float2*)&sctxT[k*GQ + g0 + 2]), w2, a1);
        }
        float o0,o1,o2,o3;
        upk(o0,o1,a0); upk(o2,o3,a1);
        float yv[4];
        yv[0] = sfeatT[c*GQ + g0+0] + o0;
        yv[1] = sfeatT[c*GQ + g0+1] + o1;
        yv[2] = sfeatT[c*GQ + g0+2] + o2;
        yv[3] = sfeatT[c*GQ + g0+3] + o3;

        int warp = t >> 5, lane = t & 31, w4 = warp & 3;
        #pragma unroll
        for (int gg = 0; gg < 4; gg++) {
            float s = yv[gg], ss = yv[gg]*yv[gg];
            for (int o = 16; o; o >>= 1) {
                s  += __shfl_xor_sync(~0u, s, o);
                ss += __shfl_xor_sync(~0u, ss, o);
            }
            if (lane == 0) {
                sred[(g0+gg)*4 + w4]      = s;
                sred[32 + (g0+gg)*4 + w4] = ss;
            }
        }
        __syncthreads();
        float lg = lng[c], lb = lnb[c];
        #pragma unroll
        for (int gg = 0; gg < 4; gg++) {
            int g = g0 + gg;
            float s  = sred[g*4+0] + sred[g*4+1] + sred[g*4+2] + sred[g*4+3];
            float ss = sred[32+g*4+0] + sred[32+g*4+1] + sred[32+g*4+2] + sred[32+g*4+3];
            float mu = s * (1.f/CC), var = ss * (1.f/CC) - mu*mu;
            g_y[(n0+g)*CC + c] = (yv[gg] - mu) * rsqrtf(var + EPSF) * lg + lb;
        }
    }
}

// ================= submanifold 3^3 conv (simple, round-3 proven) ===========
__global__ void __launch_bounds__(320, 2)
k_conv(const int* __restrict__ idx, const float* __restrict__ segw,
       const float* __restrict__ segb, float* __restrict__ out) {
    __shared__ float sW[CC*NCL];
    __shared__ int4 svox[32];
    int t = threadIdx.x;
    int n0 = blockIdx.x * 32;
    if (t < 32) svox[t] = ((const int4*)idx)[n0 + t];
    __syncthreads();
    int v = t / 10, op = t - v * 10;     // 32 voxels x 10 oc-pairs
    int4 pv = svox[v];
    float2 bb = *(const float2*)&segb[op*2];
    ull acc0 = pk(bb.x, bb.y), acc1 = 0ull;
    for (int d = 0; d < 27; d++) {
        for (int i = t; i < CC*NCL; i += 320) sW[i] = segw[d*CC*NCL + i];
        __syncthreads();
        int ax = d / 9, ay = (d / 3) % 3, az = d % 3;
        int x = pv.y + ax - 1, y = pv.z + ay - 1, z = pv.w + az - 1;
        if (x >= 0 && x < GXD && y >= 0 && y < GYD && z >= 0 && z < GZD) {
            int m = g_map[((pv.x * GXD + x) * GYD + y) * GZD + z];
            if (m > 0) {
                const float* yr = &g_y[(m-1)*CC];
                #pragma unroll 8
                for (int c2 = 0; c2 < CC; c2 += 2) {
                    float y0 = yr[c2], y1 = yr[c2+1];
                    FMA2(acc0, pk(y0, y0), pk2(*(const float2*)&sW[c2*NCL + op*2]),     acc0);
                    FMA2(acc1, pk(y1, y1), pk2(*(const float2*)&sW[(c2+1)*NCL + op*2]), acc1);
                }
            }
        }
        __syncthreads();
    }
    float a0, a1, b0, b1;
    upk(a0, a1, acc0); upk(b0, b1, acc1);
    float2 res; res.x = a0 + b0; res.y = a1 + b1;
    *(float2*)&out[(n0 + v)*NCL + op*2] = res;
}

// --------------------------------------------------------------------------
extern "C" void kernel_launch(void* const* d_in, const int* in_sizes, int n_in,
                              void* d_out, int out_size) {
    const int*   idx  = (const int*)  d_in[0];
    const float* feat = (const float*)d_in[1];
    const float* cw1  = (const float*)d_in[2];
    const float* cb1  = (const float*)d_in[3];
    const float* cg1  = (const float*)d_in[4];
    const float* cbe1 = (const float*)d_in[5];
    const float* cw2  = (const float*)d_in[6];
    const float* cb2  = (const float*)d_in[7];
    const float* pw1  = (const float*)d_in[8];
    const float* pb1  = (const float*)d_in[9];
    const float* pg1  = (const float*)d_in[10];
    const float* pbe1 = (const float*)d_in[11];
    const float* pw2  = (const float*)d_in[12];
    const float* pb2  = (const float*)d_in[13];
    const float* wq   = (const float*)d_in[14];
    const float* bq   = (const float*)d_in[15];
    const float* wk   = (const float*)d_in[16];
    const float* bk   = (const float*)d_in[17];
    const float* wv   = (const float*)d_in[18];
    const float* bv   = (const float*)d_in[19];
    const float* wo   = (const float*)d_in[20];
    const float* bo   = (const float*)d_in[21];
    const float* ln_g = (const float*)d_in[22];
    const float* ln_b = (const float*)d_in[23];
    const float* segw = (const float*)d_in[24];
    const float* segb = (const float*)d_in[25];

    void* p_acc;
    cudaGetSymbolAddress(&p_acc, g_acc);

    constexpr int ATTN_SMEM = (CC*GQ*3 + NH*NSV*GQ + 64*GQ + 256 + 64 + 64 + 24 + 8) * 4;
    cudaFuncSetAttribute(k_attn, cudaFuncAttributeMaxDynamicSharedMemorySize, ATTN_SMEM);

    cudaMemsetAsync(p_acc, 0, sizeof(Acc), 0);

    k_prep    <<<1, 256>>>(idx, pw1, pb1, pg1, pbe1);
    k_sgemm1  <<<NSV, 512>>>(feat, cw1, cb1);
    k_gemm2kv <<<NSV, 512>>>(cw2, cb2, cg1, cbe1, wk, bk, wv, bv);
    k_attn    <<<NV/GQ, 256, ATTN_SMEM>>>(idx, feat, wq, bq, wo, bo, ln_g, ln_b, pw2, pb2);
    k_conv    <<<NV/32, 320>>>(idx, segw, segb, (float*)d_out);
}

// round 6
// speedup vs baseline: 1.0957x; 1.0532x over previous
#include <cuda_runtime.h>

#define NV   4096
#define NSV  256
#define BB   2
#define GXD  128
#define GYD  128
#define GZD  16
#define CC   128
#define NCL  20
#define NH   8
#define DHD  16
#define MAPSZ (BB*GXD*GYD*GZD)
#define EPSF 1e-5f
#define GQ   8

// ---------------- packed f32x2 helpers ----------------
typedef unsigned long long ull;
__device__ __forceinline__ ull pk(float lo, float hi) {
    ull r; asm("mov.b64 %0, {%1,%2};" : "=l"(r) : "f"(lo), "f"(hi)); return r;
}
__device__ __forceinline__ void upk(float& lo, float& hi, ull v) {
    asm("mov.b64 {%0,%1}, %2;" : "=f"(lo), "=f"(hi) : "l"(v));
}
#define FMA2(d,a,b,c) asm("fma.rn.f32x2 %0, %1, %2, %3;" : "=l"(d) : "l"(a), "l"(b), "l"(c))

// ---------------- device scratch ----------------
struct Acc { float s1[CC]; float s2[CC]; };
__device__ Acc  g_acc;
__device__ int4 g_unq[NSV];
__device__ int  g_members[NSV*16];
__device__ float g_hid[NSV*CC];
__device__ float g_kT[CC*NSV];
__device__ float g_vT[CC*NSV];
__device__ float g_y[NV*CC];
__device__ int   g_map[MAPSZ];          // zero-init; stores n+1 (idempotent per input)
__device__ float g_pweff[4*64];

// ================= k_prep: keys, unique, members, pbias BN fold ===========
__global__ void k_prep(const int* __restrict__ idx,
                       const float* __restrict__ pw1, const float* __restrict__ pb1,
                       const float* __restrict__ pg1, const float* __restrict__ pbe1) {
    __shared__ unsigned sflags[256];
    __shared__ unsigned short skeys[NV];
    __shared__ int sscan[256], srank[256], scnt[256];
    __shared__ long long wred[8];
    __shared__ double Si[9], Su[9], md[3], Cv[3][3];
    int t = threadIdx.x, lane = t & 31, wid = t >> 5;

    sflags[t] = 0u;
    scnt[t] = 0;
    __syncthreads();

    long long m[9] = {0,0,0,0,0,0,0,0,0};
    for (int i = t; i < NV; i += 256) {
        int4 p = ((const int4*)idx)[i];
        int key = ((p.x * 32 + (p.y >> 2)) * 32 + (p.z >> 2)) * 4 + (p.w >> 2);
        skeys[i] = (unsigned short)key;
        atomicOr(&sflags[key >> 5], 1u << (key & 31));
        g_map[((p.x * GXD + p.y) * GYD + p.z) * GZD + p.w] = i + 1;
        long long xs = p.y, ys = p.z, zs = p.w;
        m[0]+=xs; m[1]+=ys; m[2]+=zs; m[3]+=xs*xs; m[4]+=ys*ys; m[5]+=zs*zs;
        m[6]+=xs*ys; m[7]+=xs*zs; m[8]+=ys*zs;
    }
    __syncthreads();

    unsigned w = sflags[t];
    int cnt = __popc(w);
    sscan[t] = cnt; __syncthreads();
    for (int off = 1; off < 256; off <<= 1) {
        int v = (t >= off) ? sscan[t - off] : 0;
        __syncthreads(); sscan[t] += v; __syncthreads();
    }
    int excl = sscan[t] - cnt;
    srank[t] = excl;
    unsigned wb = w;
    while (wb) {
        int bit = __ffs(wb) - 1; wb &= wb - 1;
        int rank = excl + __popc(w & ((1u << bit) - 1u));
        int key = t * 32 + bit;
        int4 u;
        u.w = key & 3; u.z = (key >> 2) & 31; u.y = (key >> 7) & 31; u.x = key >> 12;
        g_unq[rank] = u;
    }
    __syncthreads();

    // member lists: 16 voxels per supervoxel
    for (int i = t; i < NV; i += 256) {
        int key = skeys[i];
        int s = srank[key >> 5] + __popc(sflags[key >> 5] & ((1u << (key & 31)) - 1u));
        int slot = atomicAdd(&scnt[s], 1);
        g_members[s*16 + slot] = i;
    }

    for (int k = 0; k < 9; k++) {
        long long v = m[k];
        for (int o = 16; o; o >>= 1) v += __shfl_xor_sync(~0u, v, o);
        if (lane == 0) wred[wid] = v;
        __syncthreads();
        if (t == 0) { long long s = 0; for (int i = 0; i < 8; i++) s += wred[i]; Si[k] = (double)s; }
        __syncthreads();
    }
    {
        int4 u = g_unq[t];
        long long xs = u.y, ys = u.z, zs = u.w;
        long long mu9[9] = { xs, ys, zs, xs*xs, ys*ys, zs*zs, xs*ys, xs*zs, ys*zs };
        for (int k = 0; k < 9; k++) {
            long long v = mu9[k];
            for (int o = 16; o; o >>= 1) v += __shfl_xor_sync(~0u, v, o);
            if (lane == 0) wred[wid] = v;
            __syncthreads();
            if (t == 0) { long long s = 0; for (int i = 0; i < 8; i++) s += wred[i]; Su[k] = (double)s; }
            __syncthreads();
        }
    }
    if (t == 0) {
        double mi[3], mu_[3];
        for (int a = 0; a < 3; a++) {
            mi[a]  = Si[a] / (double)NV;
            mu_[a] = Su[a] / (double)NSV;
            md[a]  = mi[a] - mu_[a];
        }
        const int pid[3][3] = { {3,6,7}, {6,4,8}, {7,8,5} };
        for (int a = 0; a < 3; a++)
            for (int b = 0; b < 3; b++)
                Cv[a][b] = (Si[pid[a][b]] / (double)NV  - mi[a]  * mi[b])
                         + (Su[pid[a][b]] / (double)NSV - mu_[a] * mu_[b]);
    }
    __syncthreads();
    if (t < 64) {
        int j = t;
        double w3[3];
        for (int a = 0; a < 3; a++) w3[a] = (double)pw1[a*64 + j];
        double mu = md[0]*w3[0] + md[1]*w3[1] + md[2]*w3[2] + (double)pb1[j];
        double var = 0.0;
        for (int a = 0; a < 3; a++)
            for (int b = 0; b < 3; b++)
                var += w3[a] * Cv[a][b] * w3[b];
        float s = rsqrtf((float)var + EPSF) * pg1[j];
        for (int a = 0; a < 3; a++) g_pweff[a*64 + j] = (float)w3[a] * s;
        g_pweff[192 + j] = (float)((double)pb1[j] - mu) * s + pbe1[j];
    }
}

// ================= fused softmax-scatter + gemm1 + BN stats ================
__global__ void __launch_bounds__(512, 2)
k_sgemm1(const float* __restrict__ feat,
         const float* __restrict__ cw1, const float* __restrict__ cb1) {
    __shared__ float sft[16][CC];
    __shared__ float cfr[CC];
    __shared__ float pred[4][CC];
    int t = threadIdx.x, s = blockIdx.x;
    int wrp = t >> 5, lane = t & 31;

    {
        int row = g_members[s*16 + wrp];
        float4 v = *(const float4*)&feat[row*CC + lane*4];
        float m = fmaxf(fmaxf(v.x, v.y), fmaxf(v.z, v.w));
        for (int o = 16; o; o >>= 1) m = fmaxf(m, __shfl_xor_sync(~0u, m, o));
        float e0 = __expf(v.x - m), e1 = __expf(v.y - m);
        float e2 = __expf(v.z - m), e3 = __expf(v.w - m);
        float sum = e0 + e1 + e2 + e3;
        for (int o = 16; o; o >>= 1) sum += __shfl_xor_sync(~0u, sum, o);
        float inv = 1.f / sum;
        float4 r; r.x = e0*inv; r.y = e1*inv; r.z = e2*inv; r.w = e3*inv;
        *(float4*)&sft[wrp][lane*4] = r;
    }
    __syncthreads();
    if (t < CC) {
        float a = 0.f;
        #pragma unroll
        for (int r = 0; r < 16; r++) a += sft[r][t];
        cfr[t] = a;
    }
    __syncthreads();
    {
        int c = t & (CC-1), ks = t >> 7;
        float acc = 0.f;
        int k0 = ks * 32;
        #pragma unroll 8
        for (int k = k0; k < k0 + 32; k++)
            acc = fmaf(cfr[k], cw1[k*CC + c], acc);
        pred[ks][c] = acc;
    }
    __syncthreads();
    if (t < CC) {
        float v = pred[0][t] + pred[1][t] + pred[2][t] + pred[3][t] + cb1[t];
        g_hid[s*CC + t] = v;
        atomicAdd(&g_acc.s1[t], v);
        atomicAdd(&g_acc.s2[t], v*v);
    }
}

// ================= BN+ReLU + gemm2 + K,V projections (k-split) =============
__global__ void __launch_bounds__(512, 2)
k_gemm2kv(const float* __restrict__ cw2, const float* __restrict__ cb2,
          const float* __restrict__ cg1, const float* __restrict__ cbe1,
          const float* __restrict__ wk,  const float* __restrict__ bk,
          const float* __restrict__ wv,  const float* __restrict__ bv) {
    __shared__ float act[CC], hrow[CC];
    __shared__ float pr[4][CC];
    int t = threadIdx.x, r = blockIdx.x;

    if (t < CC) {
        float mu  = g_acc.s1[t] * (1.f/NSV);
        float var = g_acc.s2[t] * (1.f/NSV) - mu * mu;
        float A = cg1[t] * rsqrtf(var + EPSF);
        float D = cbe1[t] - mu * A;
        act[t] = fmaxf(fmaf(g_hid[r*CC + t], A, D), 0.f);
    }
    __syncthreads();
    {
        int c = t & (CC-1), ks = t >> 7;
        float acc = 0.f;
        int k0 = ks * 32;
        #pragma unroll 8
        for (int k = k0; k < k0 + 32; k++)
            acc = fmaf(act[k], cw2[k*CC + c], acc);
        pr[ks][c] = acc;
    }
    __syncthreads();
    if (t < CC) hrow[t] = pr[0][t] + pr[1][t] + pr[2][t] + pr[3][t] + cb2[t];
    __syncthreads();
    {
        int c = t & (CC-1), sel = t >> 7;
        const float* W = (sel < 2) ? wk : wv;
        int k0 = (sel & 1) * 64;
        float acc = 0.f;
        #pragma unroll 8
        for (int k = k0; k < k0 + 64; k++)
            acc = fmaf(hrow[k], W[k*CC + c], acc);
        pr[sel][c] = acc;
    }
    __syncthreads();
    if (t < 2*CC) {
        int c = t & (CC-1), proj = t >> 7;
        float val = pr[proj*2][c] + pr[proj*2+1][c] + (proj ? bv[c] : bk[c]);
        (proj ? g_vT : g_kT)[c*NSV + r] = val;
    }
}

// ================= fully fused attention (register-tiled, f32x2) ===========
// smem float layout (offsets in floats):
//  sfeatT [k][g]   0      .. 1024
//  sqT    [c][g]   1024   .. 2048
//  satt   [h][g][s]2048   .. 18432    (s contiguous!)
//  sctxT  [k][g]   18432  .. 19456
//  spb    [s][g]   19456  .. 21504
//  st     [j][g]   21504  .. 22016
//  sw4    [j][4]   22016  .. 22272   {w0,w1,w2,b}
//  spw2   [j]      22272  .. 22336
//  sred            22336  .. 22400
//  spos            22400  .. 22424
#define ATTN_FLOATS 22424
__global__ void __launch_bounds__(256, 2)
k_attn(const int* __restrict__ idx, const float* __restrict__ feat,
       const float* __restrict__ wq, const float* __restrict__ bq,
       const float* __restrict__ wo, const float* __restrict__ bo,
       const float* __restrict__ lng, const float* __restrict__ lnb,
       const float* __restrict__ pw2, const float* __restrict__ pb2) {
    extern __shared__ float sm[];
    float* sfeatT = sm;
    float* sqT    = sm + 1024;
    float* satt   = sm + 2048;
    float* sctxT  = sm + 18432;
    float* spb    = sm + 19456;
    float* st     = sm + 21504;
    float* sw4    = sm + 22016;
    float* spw2   = sm + 22272;
    float* sred   = sm + 22336;
    float* spos   = sm + 22400;

    int t = threadIdx.x;
    int n0 = blockIdx.x * GQ;
    int c = t & (CC-1), grp = t >> 7, g0 = grp * 4;

    // ---- phase 1: stage constants + features ----
    { int j = t >> 2, a = t & 3; sw4[t] = g_pweff[a*64 + j]; }
    if (t < 64) spw2[t] = pw2[t];
    if (t < GQ*3) spos[t] = (float)idx[(n0 + t/3)*4 + 1 + (t%3)];
    #pragma unroll
    for (int i = 0; i < 4; i++) {
        int li = t + 256*i;
        sfeatT[(li & (CC-1))*GQ + (li >> 7)] = feat[n0*CC + li];
    }
    __syncthreads();

    // ---- phase 2: t_j(g) table ----
    #pragma unroll
    for (int p = t; p < 64*GQ; p += 256) {
        int j = p >> 3, g = p & 7;
        float4 w = *(const float4*)&sw4[j*4];
        st[p] = fmaf(spos[g*3], w.x, fmaf(spos[g*3+1], w.y, fmaf(spos[g*3+2], w.z, w.w)));
    }
    __syncthreads();

    // ---- phase 3: q projection (scale 0.25 folded) ----
    {
        float b = bq[c];
        ull a01 = pk(b, b), a23 = pk(b, b);
        #pragma unroll 4
        for (int k = 0; k < CC; k++) {
            float w = wq[k*CC + c];
            ull wd = pk(w, w);
            float4 f = *(const float4*)&sfeatT[k*GQ + g0];
            FMA2(a01, pk(f.x, f.y), wd, a01);
            FMA2(a23, pk(f.z, f.w), wd, a23);
        }
        float q0,q1,q2,q3;
        upk(q0,q1,a01); upk(q2,q3,a23);
        float4 qo; qo.x = q0*0.25f; qo.y = q1*0.25f; qo.z = q2*0.25f; qo.w = q3*0.25f;
        *(float4*)&sqT[c*GQ + g0] = qo;
    }
    __syncthreads();

    // ---- phase 4: pbias -> spb[s][g] ----
    {
        int4 u = g_unq[t];
        float ux = (float)u.y, uy = (float)u.z, uz = (float)u.w;
        float pbv = pb2[0];
        float pb[8];
        #pragma unroll
        for (int g = 0; g < 8; g++) pb[g] = pbv;
        #pragma unroll 2
        for (int j = 0; j < 64; j++) {
            float4 w = *(const float4*)&sw4[j*4];
            float uj = fmaf(ux, w.x, fmaf(uy, w.y, uz * w.z));
            float w2j = spw2[j];
            float4 tA = *(const float4*)&st[j*8];
            float4 tB = *(const float4*)&st[j*8 + 4];
            pb[0] = fmaf(fmaxf(tA.x - uj, 0.f), w2j, pb[0]);
            pb[1] = fmaf(fmaxf(tA.y - uj, 0.f), w2j, pb[1]);
            pb[2] = fmaf(fmaxf(tA.z - uj, 0.f), w2j, pb[2]);
            pb[3] = fmaf(fmaxf(tA.w - uj, 0.f), w2j, pb[3]);
            pb[4] = fmaf(fmaxf(tB.x - uj, 0.f), w2j, pb[4]);
            pb[5] = fmaf(fmaxf(tB.y - uj, 0.f), w2j, pb[5]);
            pb[6] = fmaf(fmaxf(tB.z - uj, 0.f), w2j, pb[6]);
            pb[7] = fmaf(fmaxf(tB.w - uj, 0.f), w2j, pb[7]);
        }
        float4 wA; wA.x = pb[0]; wA.y = pb[1]; wA.z = pb[2]; wA.w = pb[3];
        float4 wB; wB.x = pb[4]; wB.y = pb[5]; wB.z = pb[6]; wB.w = pb[7];
        *(float4*)&spb[t*8]     = wA;
        *(float4*)&spb[t*8 + 4] = wB;
    }
    __syncthreads();

    // ---- phase 5: scores. thread = (head, s-octile); acc packs s-pairs ----
    {
        int h = t >> 5, ln = t & 31;
        int s0 = ln * 8;
        ull acc[8][4];     // [g][s-pair]
        #pragma unroll
        for (int sp = 0; sp < 4; sp++) {
            const float* rA = &spb[(s0 + 2*sp) * 8];
            const float* rB = rA + 8;
            float4 a0 = *(const float4*)rA, a1 = *(const float4*)(rA+4);
            float4 b0 = *(const float4*)rB, b1 = *(const float4*)(rB+4);
            acc[0][sp] = pk(a0.x, b0.x);
            acc[1][sp] = pk(a0.y, b0.y);
            acc[2][sp] = pk(a0.z, b0.z);
            acc[3][sp] = pk(a0.w, b0.w);
            acc[4][sp] = pk(a1.x, b1.x);
            acc[5][sp] = pk(a1.y, b1.y);
            acc[6][sp] = pk(a1.z, b1.z);
            acc[7][sp] = pk(a1.w, b1.w);
        }
        #pragma unroll 4
        for (int c16 = 0; c16 < DHD; c16++) {
            int cix = h*DHD + c16;
            float4 qA = *(const float4*)&sqT[cix*GQ];
            float4 qB = *(const float4*)&sqT[cix*GQ + 4];
            float4 k03 = *(const float4*)&g_kT[cix*NSV + s0];
            float4 k47 = *(const float4*)&g_kT[cix*NSV + s0 + 4];
            ull kp0 = pk(k03.x, k03.y), kp1 = pk(k03.z, k03.w);
            ull kp2 = pk(k47.x, k47.y), kp3 = pk(k47.z, k47.w);
            float qs[8] = {qA.x,qA.y,qA.z,qA.w,qB.x,qB.y,qB.z,qB.w};
            #pragma unroll
            for (int g = 0; g < 8; g++) {
                ull qd = pk(qs[g], qs[g]);
                FMA2(acc[g][0], kp0, qd, acc[g][0]);
                FMA2(acc[g][1], kp1, qd, acc[g][1]);
                FMA2(acc[g][2], kp2, qd, acc[g][2]);
                FMA2(acc[g][3], kp3, qd, acc[g][3]);
            }
        }
        #pragma unroll
        for (int g = 0; g < 8; g++) {
            float x0,x1,x2,x3,x4,x5,x6,x7;
            upk(x0,x1,acc[g][0]); upk(x2,x3,acc[g][1]);
            upk(x4,x5,acc[g][2]); upk(x6,x7,acc[g][3]);
            float4 w0; w0.x=x0; w0.y=x1; w0.z=x2; w0.w=x3;
            float4 w1; w1.x=x4; w1.y=x5; w1.z=x6; w1.w=x7;
            float* row = &satt[(h*8 + g)*NSV];
            *(float4*)&row[s0]     = w0;
            *(float4*)&row[s0 + 4] = w1;
        }
    }
    __syncthreads();

    // ---- phase 6: softmax over 64 contiguous rows ----
    {
        int warp = t >> 5, lane = t & 31;
        #pragma unroll
        for (int r = warp; r < GQ*NH; r += 8) {
            float* row = satt + r*NSV;
            float vals[8];
            float m = -1e30f;
            #pragma unroll
            for (int k = 0; k < 8; k++) { vals[k] = row[lane + 32*k]; m = fmaxf(m, vals[k]); }
            for (int o = 16; o; o >>= 1) m = fmaxf(m, __shfl_xor_sync(~0u, m, o));
            float sum = 0.f;
            #pragma unroll
            for (int k = 0; k < 8; k++) { vals[k] = __expf(vals[k] - m); sum += vals[k]; }
            for (int o = 16; o; o >>= 1) sum += __shfl_xor_sync(~0u, sum, o);
            float inv = 1.f / sum;
            #pragma unroll
            for (int k = 0; k < 8; k++) row[lane + 32*k] = vals[k] * inv;
        }
    }
    __syncthreads();

    // ---- phase 7: attn @ V (all float4; acc packs s-pairs, hadd at end) ----
    {
        int hh = c >> 4;
        const float* a0r = &satt[(hh*8 + g0)*NSV];
        const float* a1r = a0r + NSV;
        const float* a2r = a0r + 2*NSV;
        const float* a3r = a0r + 3*NSV;
        const float4* vrow = (const float4*)&g_vT[c*NSV];
        ull A0 = 0ull, A1 = 0ull, A2 = 0ull, A3 = 0ull;
        #pragma unroll 4
        for (int s4 = 0; s4 < NSV/4; s4++) {
            float4 vv = vrow[s4];
            ull vlo = pk(vv.x, vv.y), vhi = pk(vv.z, vv.w);
            float4 aa = *(const float4*)&a0r[s4*4];
            FMA2(A0, pk(aa.x, aa.y), vlo, A0);
            FMA2(A0, pk(aa.z, aa.w), vhi, A0);
            float4 ab = *(const float4*)&a1r[s4*4];
            FMA2(A1, pk(ab.x, ab.y), vlo, A1);
            FMA2(A1, pk(ab.z, ab.w), vhi, A1);
            float4 ac = *(const float4*)&a2r[s4*4];
            FMA2(A2, pk(ac.x, ac.y), vlo, A2);
            FMA2(A2, pk(ac.z, ac.w), vhi, A2);
            float4 ad = *(const float4*)&a3r[s4*4];
            FMA2(A3, pk(ad.x, ad.y), vlo, A3);
            FMA2(A3, pk(ad.z, ad.w), vhi, A3);
        }
        float p0, p1;
        float4 cw;
        upk(p0, p1, A0); cw.x = p0 + p1;
        upk(p0, p1, A1); cw.y = p0 + p1;
        upk(p0, p1, A2); cw.z = p0 + p1;
        upk(p0, p1, A3); cw.w = p0 + p1;
        *(float4*)&sctxT[c*GQ + g0] = cw;
    }
    __syncthreads();

    // ---- phase 8: o-proj + residual + LayerNorm ----
    {
        float b = bo[c];
        ull a01 = pk(b, b), a23 = pk(b, b);
        #pragma unroll 4
        for (int k = 0; k < CC; k++) {
            float w = wo[k*CC + c];
            ull wd = pk(w, w);
            float4 cx = *(const float4*)&sctxT[k*GQ + g0];
            FMA2(a01, pk(cx.x, cx.y), wd, a01);
            FMA2(a23, pk(cx.z, cx.w), wd, a23);
        }
        float o0,o1,o2,o3;
        upk(o0,o1,a01); upk(o2,o3,a23);
        float yv[4];
        float4 fr = *(const float4*)&sfeatT[c*GQ + g0];
        yv[0] = fr.x + o0; yv[1] = fr.y + o1; yv[2] = fr.z + o2; yv[3] = fr.w + o3;

        int warp = t >> 5, lane = t & 31, w4 = warp & 3;
        #pragma unroll
        for (int gg = 0; gg < 4; gg++) {
            float s = yv[gg], ss = yv[gg]*yv[gg];
            for (int o = 16; o; o >>= 1) {
                s  += __shfl_xor_sync(~0u, s, o);
                ss += __shfl_xor_sync(~0u, ss, o);
            }
            if (lane == 0) {
                sred[(g0+gg)*4 + w4]      = s;
                sred[32 + (g0+gg)*4 + w4] = ss;
            }
        }
        __syncthreads();
        float lg = lng[c], lb = lnb[c];
        #pragma unroll
        for (int gg = 0; gg < 4; gg++) {
            int g = g0 + gg;
            float s  = sred[g*4+0] + sred[g*4+1] + sred[g*4+2] + sred[g*4+3];
            float ss = sred[32+g*4+0] + sred[32+g*4+1] + sred[32+g*4+2] + sred[32+g*4+3];
            float mu = s * (1.f/CC), var = ss * (1.f/CC) - mu*mu;
            g_y[(n0+g)*CC + c] = (yv[gg] - mu) * rsqrtf(var + EPSF) * lg + lb;
        }
    }
}

// ================= submanifold 3^3 conv =====================================
__global__ void __launch_bounds__(320, 2)
k_conv(const int* __restrict__ idx, const float* __restrict__ segw,
       const float* __restrict__ segb, float* __restrict__ out) {
    __shared__ float sW[CC*NCL];
    __shared__ int4 svox[32];
    int t = threadIdx.x;
    int n0 = blockIdx.x * 32;
    if (t < 32) svox[t] = ((const int4*)idx)[n0 + t];
    __syncthreads();
    int v = t / 10, op = t - v * 10;
    int4 pv = svox[v];
    float2 bb = *(const float2*)&segb[op*2];
    ull acc0 = pk(bb.x, bb.y), acc1 = 0ull;
    for (int d = 0; d < 27; d++) {
        for (int i = t; i < CC*NCL; i += 320) sW[i] = segw[d*CC*NCL + i];
        __syncthreads();
        int ax = d / 9, ay = (d / 3) % 3, az = d % 3;
        int x = pv.y + ax - 1, y = pv.z + ay - 1, z = pv.w + az - 1;
        if (x >= 0 && x < GXD && y >= 0 && y < GYD && z >= 0 && z < GZD) {
            int m = g_map[((pv.x * GXD + x) * GYD + y) * GZD + z];
            if (m > 0) {
                const float* yr = &g_y[(m-1)*CC];
                #pragma unroll 8
                for (int c2 = 0; c2 < CC; c2 += 2) {
                    float y0 = yr[c2], y1 = yr[c2+1];
                    FMA2(acc0, pk(y0, y0), pk(sW[c2*NCL + op*2], sW[c2*NCL + op*2 + 1]),     acc0);
                    FMA2(acc1, pk(y1, y1), pk(sW[(c2+1)*NCL + op*2], sW[(c2+1)*NCL + op*2 + 1]), acc1);
                }
            }
        }
        __syncthreads();
    }
    float a0, a1, b0, b1;
    upk(a0, a1, acc0); upk(b0, b1, acc1);
    float2 res; res.x = a0 + b0; res.y = a1 + b1;
    *(float2*)&out[(n0 + v)*NCL + op*2] = res;
}

// --------------------------------------------------------------------------
extern "C" void kernel_launch(void* const* d_in, const int* in_sizes, int n_in,
                              void* d_out, int out_size) {
    const int*   idx  = (const int*)  d_in[0];
    const float* feat = (const float*)d_in[1];
    const float* cw1  = (const float*)d_in[2];
    const float* cb1  = (const float*)d_in[3];
    const float* cg1  = (const float*)d_in[4];
    const float* cbe1 = (const float*)d_in[5];
    const float* cw2  = (const float*)d_in[6];
    const float* cb2  = (const float*)d_in[7];
    const float* pw1  = (const float*)d_in[8];
    const float* pb1  = (const float*)d_in[9];
    const float* pg1  = (const float*)d_in[10];
    const float* pbe1 = (const float*)d_in[11];
    const float* pw2  = (const float*)d_in[12];
    const float* pb2  = (const float*)d_in[13];
    const float* wq   = (const float*)d_in[14];
    const float* bq   = (const float*)d_in[15];
    const float* wk   = (const float*)d_in[16];
    const float* bk   = (const float*)d_in[17];
    const float* wv   = (const float*)d_in[18];
    const float* bv   = (const float*)d_in[19];
    const float* wo   = (const float*)d_in[20];
    const float* bo   = (const float*)d_in[21];
    const float* ln_g = (const float*)d_in[22];
    const float* ln_b = (const float*)d_in[23];
    const float* segw = (const float*)d_in[24];
    const float* segb = (const float*)d_in[25];

    void* p_acc;
    cudaGetSymbolAddress(&p_acc, g_acc);

    constexpr int ATTN_SMEM = ATTN_FLOATS * 4;
    cudaFuncSetAttribute(k_attn, cudaFuncAttributeMaxDynamicSharedMemorySize, ATTN_SMEM);

    cudaMemsetAsync(p_acc, 0, sizeof(Acc), 0);

    k_prep    <<<1, 256>>>(idx, pw1, pb1, pg1, pbe1);
    k_sgemm1  <<<NSV, 512>>>(feat, cw1, cb1);
    k_gemm2kv <<<NSV, 512>>>(cw2, cb2, cg1, cbe1, wk, bk, wv, bv);
    k_attn    <<<NV/GQ, 256, ATTN_SMEM>>>(idx, feat, wq, bq, wo, bo, ln_g, ln_b, pw2, pb2);
    k_conv    <<<NV/32, 320>>>(idx, segw, segb, (float*)d_out);
}

// round 7
// speedup vs baseline: 1.2261x; 1.1190x over previous
#include <cuda_runtime.h>

#define NV   4096
#define NSV  256
#define BB   2
#define GXD  128
#define GYD  128
#define GZD  16
#define CC   128
#define NCL  20
#define NH   8
#define DHD  16
#define MAPSZ (BB*GXD*GYD*GZD)
#define EPSF 1e-5f
#define GQ   8

// ---------------- packed f32x2 helpers ----------------
typedef unsigned long long ull;
__device__ __forceinline__ ull pk(float lo, float hi) {
    ull r; asm("mov.b64 %0, {%1,%2};" : "=l"(r) : "f"(lo), "f"(hi)); return r;
}
__device__ __forceinline__ void upk(float& lo, float& hi, ull v) {
    asm("mov.b64 {%0,%1}, %2;" : "=f"(lo), "=f"(hi) : "l"(v));
}
#define FMA2(d,a,b,c) asm("fma.rn.f32x2 %0, %1, %2, %3;" : "=l"(d) : "l"(a), "l"(b), "l"(c))

// ---------------- device scratch ----------------
struct Acc { float s1[CC]; float s2[CC]; };
__device__ Acc  g_acc;
__device__ int4 g_unq[NSV];
__device__ int  g_members[NSV*16];
__device__ float g_hid[NSV*CC];
__device__ float g_kT[CC*NSV];     // K transposed [c][s]
__device__ float g_v[NSV*CC];      // V natural    [s][c]  (coalesced AV reads)
__device__ float g_y[NV*CC];
__device__ int   g_map[MAPSZ];     // zero-init; stores n+1 (idempotent per input)
__device__ float g_pweff[4*64];

// ================= k_prep: keys, unique, members, pbias BN fold ===========
__global__ void k_prep(const int* __restrict__ idx,
                       const float* __restrict__ pw1, const float* __restrict__ pb1,
                       const float* __restrict__ pg1, const float* __restrict__ pbe1) {
    __shared__ unsigned sflags[256];
    __shared__ unsigned short skeys[NV];
    __shared__ int sscan[256], srank[256], scnt[256];
    __shared__ long long wred[8];
    __shared__ double Si[9], Su[9], md[3], Cv[3][3];
    int t = threadIdx.x, lane = t & 31, wid = t >> 5;

    sflags[t] = 0u;
    scnt[t] = 0;
    __syncthreads();

    long long m[9] = {0,0,0,0,0,0,0,0,0};
    for (int i = t; i < NV; i += 256) {
        int4 p = ((const int4*)idx)[i];
        int key = ((p.x * 32 + (p.y >> 2)) * 32 + (p.z >> 2)) * 4 + (p.w >> 2);
        skeys[i] = (unsigned short)key;
        atomicOr(&sflags[key >> 5], 1u << (key & 31));
        g_map[((p.x * GXD + p.y) * GYD + p.z) * GZD + p.w] = i + 1;
        long long xs = p.y, ys = p.z, zs = p.w;
        m[0]+=xs; m[1]+=ys; m[2]+=zs; m[3]+=xs*xs; m[4]+=ys*ys; m[5]+=zs*zs;
        m[6]+=xs*ys; m[7]+=xs*zs; m[8]+=ys*zs;
    }
    __syncthreads();

    unsigned w = sflags[t];
    int cnt = __popc(w);
    sscan[t] = cnt; __syncthreads();
    for (int off = 1; off < 256; off <<= 1) {
        int v = (t >= off) ? sscan[t - off] : 0;
        __syncthreads(); sscan[t] += v; __syncthreads();
    }
    int excl = sscan[t] - cnt;
    srank[t] = excl;
    unsigned wb = w;
    while (wb) {
        int bit = __ffs(wb) - 1; wb &= wb - 1;
        int rank = excl + __popc(w & ((1u << bit) - 1u));
        int key = t * 32 + bit;
        int4 u;
        u.w = key & 3; u.z = (key >> 2) & 31; u.y = (key >> 7) & 31; u.x = key >> 12;
        g_unq[rank] = u;
    }
    __syncthreads();

    for (int i = t; i < NV; i += 256) {
        int key = skeys[i];
        int s = srank[key >> 5] + __popc(sflags[key >> 5] & ((1u << (key & 31)) - 1u));
        int slot = atomicAdd(&scnt[s], 1);
        g_members[s*16 + slot] = i;
    }

    for (int k = 0; k < 9; k++) {
        long long v = m[k];
        for (int o = 16; o; o >>= 1) v += __shfl_xor_sync(~0u, v, o);
        if (lane == 0) wred[wid] = v;
        __syncthreads();
        if (t == 0) { long long s = 0; for (int i = 0; i < 8; i++) s += wred[i]; Si[k] = (double)s; }
        __syncthreads();
    }
    {
        int4 u = g_unq[t];
        long long xs = u.y, ys = u.z, zs = u.w;
        long long mu9[9] = { xs, ys, zs, xs*xs, ys*ys, zs*zs, xs*ys, xs*zs, ys*zs };
        for (int k = 0; k < 9; k++) {
            long long v = mu9[k];
            for (int o = 16; o; o >>= 1) v += __shfl_xor_sync(~0u, v, o);
            if (lane == 0) wred[wid] = v;
            __syncthreads();
            if (t == 0) { long long s = 0; for (int i = 0; i < 8; i++) s += wred[i]; Su[k] = (double)s; }
            __syncthreads();
        }
    }
    if (t == 0) {
        double mi[3], mu_[3];
        for (int a = 0; a < 3; a++) {
            mi[a]  = Si[a] / (double)NV;
            mu_[a] = Su[a] / (double)NSV;
            md[a]  = mi[a] - mu_[a];
        }
        const int pid[3][3] = { {3,6,7}, {6,4,8}, {7,8,5} };
        for (int a = 0; a < 3; a++)
            for (int b = 0; b < 3; b++)
                Cv[a][b] = (Si[pid[a][b]] / (double)NV  - mi[a]  * mi[b])
                         + (Su[pid[a][b]] / (double)NSV - mu_[a] * mu_[b]);
    }
    __syncthreads();
    if (t < 64) {
        int j = t;
        double w3[3];
        for (int a = 0; a < 3; a++) w3[a] = (double)pw1[a*64 + j];
        double mu = md[0]*w3[0] + md[1]*w3[1] + md[2]*w3[2] + (double)pb1[j];
        double var = 0.0;
        for (int a = 0; a < 3; a++)
            for (int b = 0; b < 3; b++)
                var += w3[a] * Cv[a][b] * w3[b];
        float s = rsqrtf((float)var + EPSF) * pg1[j];
        for (int a = 0; a < 3; a++) g_pweff[a*64 + j] = (float)w3[a] * s;
        g_pweff[192 + j] = (float)((double)pb1[j] - mu) * s + pbe1[j];
    }
}

// ================= fused softmax-scatter + gemm1 + BN stats ================
__global__ void __launch_bounds__(512, 2)
k_sgemm1(const float* __restrict__ feat,
         const float* __restrict__ cw1, const float* __restrict__ cb1) {
    __shared__ float sft[16][CC];
    __shared__ float cfr[CC];
    __shared__ float pred[4][CC];
    int t = threadIdx.x, s = blockIdx.x;
    int wrp = t >> 5, lane = t & 31;

    {
        int row = g_members[s*16 + wrp];
        float4 v = *(const float4*)&feat[row*CC + lane*4];
        float m = fmaxf(fmaxf(v.x, v.y), fmaxf(v.z, v.w));
        for (int o = 16; o; o >>= 1) m = fmaxf(m, __shfl_xor_sync(~0u, m, o));
        float e0 = __expf(v.x - m), e1 = __expf(v.y - m);
        float e2 = __expf(v.z - m), e3 = __expf(v.w - m);
        float sum = e0 + e1 + e2 + e3;
        for (int o = 16; o; o >>= 1) sum += __shfl_xor_sync(~0u, sum, o);
        float inv = 1.f / sum;
        float4 r; r.x = e0*inv; r.y = e1*inv; r.z = e2*inv; r.w = e3*inv;
        *(float4*)&sft[wrp][lane*4] = r;
    }
    __syncthreads();
    if (t < CC) {
        float a = 0.f;
        #pragma unroll
        for (int r = 0; r < 16; r++) a += sft[r][t];
        cfr[t] = a;
    }
    __syncthreads();
    {
        int c = t & (CC-1), ks = t >> 7;
        float acc = 0.f;
        int k0 = ks * 32;
        #pragma unroll 8
        for (int k = k0; k < k0 + 32; k++)
            acc = fmaf(cfr[k], cw1[k*CC + c], acc);
        pred[ks][c] = acc;
    }
    __syncthreads();
    if (t < CC) {
        float v = pred[0][t] + pred[1][t] + pred[2][t] + pred[3][t] + cb1[t];
        g_hid[s*CC + t] = v;
        atomicAdd(&g_acc.s1[t], v);
        atomicAdd(&g_acc.s2[t], v*v);
    }
}

// ================= BN+ReLU + gemm2 + K,V projections (k-split) =============
__global__ void __launch_bounds__(512, 2)
k_gemm2kv(const float* __restrict__ cw2, const float* __restrict__ cb2,
          const float* __restrict__ cg1, const float* __restrict__ cbe1,
          const float* __restrict__ wk,  const float* __restrict__ bk,
          const float* __restrict__ wv,  const float* __restrict__ bv) {
    __shared__ float act[CC], hrow[CC];
    __shared__ float pr[4][CC];
    int t = threadIdx.x, r = blockIdx.x;

    if (t < CC) {
        float mu  = g_acc.s1[t] * (1.f/NSV);
        float var = g_acc.s2[t] * (1.f/NSV) - mu * mu;
        float A = cg1[t] * rsqrtf(var + EPSF);
        float D = cbe1[t] - mu * A;
        act[t] = fmaxf(fmaf(g_hid[r*CC + t], A, D), 0.f);
    }
    __syncthreads();
    {
        int c = t & (CC-1), ks = t >> 7;
        float acc = 0.f;
        int k0 = ks * 32;
        #pragma unroll 8
        for (int k = k0; k < k0 + 32; k++)
            acc = fmaf(act[k], cw2[k*CC + c], acc);
        pr[ks][c] = acc;
    }
    __syncthreads();
    if (t < CC) hrow[t] = pr[0][t] + pr[1][t] + pr[2][t] + pr[3][t] + cb2[t];
    __syncthreads();
    {
        int c = t & (CC-1), sel = t >> 7;
        const float* W = (sel < 2) ? wk : wv;
        int k0 = (sel & 1) * 64;
        float acc = 0.f;
        #pragma unroll 8
        for (int k = k0; k < k0 + 64; k++)
            acc = fmaf(hrow[k], W[k*CC + c], acc);
        pr[sel][c] = acc;
    }
    __syncthreads();
    if (t < 2*CC) {
        int c = t & (CC-1), proj = t >> 7;
        float val = pr[proj*2][c] + pr[proj*2+1][c] + (proj ? bv[c] : bk[c]);
        if (proj) g_v[r*CC + c]   = val;     // V natural [s][c]
        else      g_kT[c*NSV + r] = val;     // K transposed [c][s]
    }
}

// ================= fully fused attention (register-tiled, f32x2) ===========
// smem float layout (offsets in floats):
//  sfeatT [k][g]   0      .. 1024
//  sqT    [c][g]   1024   .. 2048
//  satt   [h][g][s]2048   .. 18432    (s contiguous)
//  sctxT  [k][g]   18432  .. 19456
//  spb    [g][s]   19456  .. 21504    (s contiguous!)
//  st     [j][g]   21504  .. 22016
//  sw4    [j][4]   22016  .. 22272   {w0,w1,w2,b}
//  spw2   [j]      22272  .. 22336
//  sred            22336  .. 22400
//  spos            22400  .. 22424
#define ATTN_FLOATS 22424
__global__ void __launch_bounds__(256, 2)
k_attn(const int* __restrict__ idx, const float* __restrict__ feat,
       const float* __restrict__ wq, const float* __restrict__ bq,
       const float* __restrict__ wo, const float* __restrict__ bo,
       const float* __restrict__ lng, const float* __restrict__ lnb,
       const float* __restrict__ pw2, const float* __restrict__ pb2) {
    extern __shared__ float sm[];
    float* sfeatT = sm;
    float* sqT    = sm + 1024;
    float* satt   = sm + 2048;
    float* sctxT  = sm + 18432;
    float* spb    = sm + 19456;
    float* st     = sm + 21504;
    float* sw4    = sm + 22016;
    float* spw2   = sm + 22272;
    float* sred   = sm + 22336;
    float* spos   = sm + 22400;

    int t = threadIdx.x;
    int n0 = blockIdx.x * GQ;
    int c = t & (CC-1), grp = t >> 7, g0 = grp * 4;

    // ---- phase 1: stage constants + features ----
    { int j = t >> 2, a = t & 3; sw4[t] = g_pweff[a*64 + j]; }
    if (t < 64) spw2[t] = pw2[t];
    if (t < GQ*3) spos[t] = (float)idx[(n0 + t/3)*4 + 1 + (t%3)];
    #pragma unroll
    for (int i = 0; i < 4; i++) {
        int li = t + 256*i;
        sfeatT[(li & (CC-1))*GQ + (li >> 7)] = feat[n0*CC + li];
    }
    __syncthreads();

    // ---- phase 2: t_j(g) table ----
    #pragma unroll
    for (int p = t; p < 64*GQ; p += 256) {
        int j = p >> 3, g = p & 7;
        float4 w = *(const float4*)&sw4[j*4];
        st[p] = fmaf(spos[g*3], w.x, fmaf(spos[g*3+1], w.y, fmaf(spos[g*3+2], w.z, w.w)));
    }
    __syncthreads();

    // ---- phase 3: q projection (scale 0.25 folded) ----
    {
        float b = bq[c];
        ull a01 = pk(b, b), a23 = pk(b, b);
        #pragma unroll 4
        for (int k = 0; k < CC; k++) {
            float w = wq[k*CC + c];
            ull wd = pk(w, w);
            float4 f = *(const float4*)&sfeatT[k*GQ + g0];
            FMA2(a01, pk(f.x, f.y), wd, a01);
            FMA2(a23, pk(f.z, f.w), wd, a23);
        }
        float q0,q1,q2,q3;
        upk(q0,q1,a01); upk(q2,q3,a23);
        float4 qo; qo.x = q0*0.25f; qo.y = q1*0.25f; qo.z = q2*0.25f; qo.w = q3*0.25f;
        *(float4*)&sqT[c*GQ + g0] = qo;
    }
    __syncthreads();

    // ---- phase 4: pbias -> spb[g][s] (s contiguous, conflict-free) ----
    {
        int4 u = g_unq[t];
        float ux = (float)u.y, uy = (float)u.z, uz = (float)u.w;
        float pbv = pb2[0];
        float pb[8];
        #pragma unroll
        for (int g = 0; g < 8; g++) pb[g] = pbv;
        #pragma unroll 2
        for (int j = 0; j < 64; j++) {
            float4 w = *(const float4*)&sw4[j*4];
            float uj = fmaf(ux, w.x, fmaf(uy, w.y, uz * w.z));
            float w2j = spw2[j];
            float4 tA = *(const float4*)&st[j*8];
            float4 tB = *(const float4*)&st[j*8 + 4];
            pb[0] = fmaf(fmaxf(tA.x - uj, 0.f), w2j, pb[0]);
            pb[1] = fmaf(fmaxf(tA.y - uj, 0.f), w2j, pb[1]);
            pb[2] = fmaf(fmaxf(tA.z - uj, 0.f), w2j, pb[2]);
            pb[3] = fmaf(fmaxf(tA.w - uj, 0.f), w2j, pb[3]);
            pb[4] = fmaf(fmaxf(tB.x - uj, 0.f), w2j, pb[4]);
            pb[5] = fmaf(fmaxf(tB.y - uj, 0.f), w2j, pb[5]);
            pb[6] = fmaf(fmaxf(tB.z - uj, 0.f), w2j, pb[6]);
            pb[7] = fmaf(fmaxf(tB.w - uj, 0.f), w2j, pb[7]);
        }
        #pragma unroll
        for (int g = 0; g < 8; g++) spb[g*NSV + t] = pb[g];
    }
    __syncthreads();

    // ---- phase 5: scores. thread = (head, s-octile); acc packs s-pairs ----
    {
        int h = t >> 5, ln = t & 31;
        int s0 = ln * 8;
        ull acc[8][4];     // [g][s-pair]
        #pragma unroll
        for (int g = 0; g < 8; g++) {
            float4 pA = *(const float4*)&spb[g*NSV + s0];
            float4 pB = *(const float4*)&spb[g*NSV + s0 + 4];
            acc[g][0] = pk(pA.x, pA.y);
            acc[g][1] = pk(pA.z, pA.w);
            acc[g][2] = pk(pB.x, pB.y);
            acc[g][3] = pk(pB.z, pB.w);
        }
        #pragma unroll 4
        for (int c16 = 0; c16 < DHD; c16++) {
            int cix = h*DHD + c16;
            float4 qA = *(const float4*)&sqT[cix*GQ];
            float4 qB = *(const float4*)&sqT[cix*GQ + 4];
            float4 k03 = *(const float4*)&g_kT[cix*NSV + s0];
            float4 k47 = *(const float4*)&g_kT[cix*NSV + s0 + 4];
            ull kp0 = pk(k03.x, k03.y), kp1 = pk(k03.z, k03.w);
            ull kp2 = pk(k47.x, k47.y), kp3 = pk(k47.z, k47.w);
            float qs[8] = {qA.x,qA.y,qA.z,qA.w,qB.x,qB.y,qB.z,qB.w};
            #pragma unroll
            for (int g = 0; g < 8; g++) {
                ull qd = pk(qs[g], qs[g]);
                FMA2(acc[g][0], kp0, qd, acc[g][0]);
                FMA2(acc[g][1], kp1, qd, acc[g][1]);
                FMA2(acc[g][2], kp2, qd, acc[g][2]);
                FMA2(acc[g][3], kp3, qd, acc[g][3]);
            }
        }
        #pragma unroll
        for (int g = 0; g < 8; g++) {
            float x0,x1,x2,x3,x4,x5,x6,x7;
            upk(x0,x1,acc[g][0]); upk(x2,x3,acc[g][1]);
            upk(x4,x5,acc[g][2]); upk(x6,x7,acc[g][3]);
            float4 w0; w0.x=x0; w0.y=x1; w0.z=x2; w0.w=x3;
            float4 w1; w1.x=x4; w1.y=x5; w1.z=x6; w1.w=x7;
            float* row = &satt[(h*8 + g)*NSV];
            *(float4*)&row[s0]     = w0;
            *(float4*)&row[s0 + 4] = w1;
        }
    }
    __syncthreads();

    // ---- phase 6: softmax over 64 contiguous rows ----
    {
        int warp = t >> 5, lane = t & 31;
        #pragma unroll
        for (int r = warp; r < GQ*NH; r += 8) {
            float* row = satt + r*NSV;
            float vals[8];
            float m = -1e30f;
            #pragma unroll
            for (int k = 0; k < 8; k++) { vals[k] = row[lane + 32*k]; m = fmaxf(m, vals[k]); }
            for (int o = 16; o; o >>= 1) m = fmaxf(m, __shfl_xor_sync(~0u, m, o));
            float sum = 0.f;
            #pragma unroll
            for (int k = 0; k < 8; k++) { vals[k] = __expf(vals[k] - m); sum += vals[k]; }
            for (int o = 16; o; o >>= 1) sum += __shfl_xor_sync(~0u, sum, o);
            float inv = 1.f / sum;
            #pragma unroll
            for (int k = 0; k < 8; k++) row[lane + 32*k] = vals[k] * inv;
        }
    }
    __syncthreads();

    // ---- phase 7: attn @ V — coalesced scalar V loads, float4 a rows ----
    {
        int hh = c >> 4;
        const float* a0r = &satt[(hh*8 + g0)*NSV];
        const float* a1r = a0r + NSV;
        const float* a2r = a0r + 2*NSV;
        const float* a3r = a0r + 3*NSV;
        ull A0 = 0ull, A1 = 0ull, A2 = 0ull, A3 = 0ull;
        #pragma unroll 4
        for (int s4 = 0; s4 < NSV/4; s4++) {
            int s = s4 * 4;
            float v0 = g_v[(s+0)*CC + c];
            float v1 = g_v[(s+1)*CC + c];
            float v2 = g_v[(s+2)*CC + c];
            float v3 = g_v[(s+3)*CC + c];
            ull vlo = pk(v0, v1), vhi = pk(v2, v3);
            float4 aa = *(const float4*)&a0r[s];
            FMA2(A0, pk(aa.x, aa.y), vlo, A0);
            FMA2(A0, pk(aa.z, aa.w), vhi, A0);
            float4 ab = *(const float4*)&a1r[s];
            FMA2(A1, pk(ab.x, ab.y), vlo, A1);
            FMA2(A1, pk(ab.z, ab.w), vhi, A1);
            float4 ac = *(const float4*)&a2r[s];
            FMA2(A2, pk(ac.x, ac.y), vlo, A2);
            FMA2(A2, pk(ac.z, ac.w), vhi, A2);
            float4 ad = *(const float4*)&a3r[s];
            FMA2(A3, pk(ad.x, ad.y), vlo, A3);
            FMA2(A3, pk(ad.z, ad.w), vhi, A3);
        }
        float p0, p1;
        float4 cw;
        upk(p0, p1, A0); cw.x = p0 + p1;
        upk(p0, p1, A1); cw.y = p0 + p1;
        upk(p0, p1, A2); cw.z = p0 + p1;
        upk(p0, p1, A3); cw.w = p0 + p1;
        *(float4*)&sctxT[c*GQ + g0] = cw;
    }
    __syncthreads();

    // ---- phase 8: o-proj + residual + LayerNorm ----
    {
        float b = bo[c];
        ull a01 = pk(b, b), a23 = pk(b, b);
        #pragma unroll 4
        for (int k = 0; k < CC; k++) {
            float w = wo[k*CC + c];
            ull wd = pk(w, w);
            float4 cx = *(const float4*)&sctxT[k*GQ + g0];
            FMA2(a01, pk(cx.x, cx.y), wd, a01);
            FMA2(a23, pk(cx.z, cx.w), wd, a23);
        }
        float o0,o1,o2,o3;
        upk(o0,o1,a01); upk(o2,o3,a23);
        float yv[4];
        float4 fr = *(const float4*)&sfeatT[c*GQ + g0];
        yv[0] = fr.x + o0; yv[1] = fr.y + o1; yv[2] = fr.z + o2; yv[3] = fr.w + o3;

        int warp = t >> 5, lane = t & 31, w4 = warp & 3;
        #pragma unroll
        for (int gg = 0; gg < 4; gg++) {
            float s = yv[gg], ss = yv[gg]*yv[gg];
            for (int o = 16; o; o >>= 1) {
                s  += __shfl_xor_sync(~0u, s, o);
                ss += __shfl_xor_sync(~0u, ss, o);
            }
            if (lane == 0) {
                sred[(g0+gg)*4 + w4]      = s;
                sred[32 + (g0+gg)*4 + w4] = ss;
            }
        }
        __syncthreads();
        float lg = lng[c], lb = lnb[c];
        #pragma unroll
        for (int gg = 0; gg < 4; gg++) {
            int g = g0 + gg;
            float s  = sred[g*4+0] + sred[g*4+1] + sred[g*4+2] + sred[g*4+3];
            float ss = sred[32+g*4+0] + sred[32+g*4+1] + sred[32+g*4+2] + sred[32+g*4+3];
            float mu = s * (1.f/CC), var = ss * (1.f/CC) - mu*mu;
            g_y[(n0+g)*CC + c] = (yv[gg] - mu) * rsqrtf(var + EPSF) * lg + lb;
        }
    }
}

// ================= submanifold 3^3 conv =====================================
__global__ void __launch_bounds__(320, 2)
k_conv(const int* __restrict__ idx, const float* __restrict__ segw,
       const float* __restrict__ segb, float* __restrict__ out) {
    __shared__ float sW[CC*NCL];
    __shared__ int4 svox[32];
    int t = threadIdx.x;
    int n0 = blockIdx.x * 32;
    if (t < 32) svox[t] = ((const int4*)idx)[n0 + t];
    __syncthreads();
    int v = t / 10, op = t - v * 10;
    int4 pv = svox[v];
    float2 bb = *(const float2*)&segb[op*2];
    ull acc0 = pk(bb.x, bb.y), acc1 = 0ull;
    for (int d = 0; d < 27; d++) {
        for (int i = t; i < CC*NCL; i += 320) sW[i] = segw[d*CC*NCL + i];
        __syncthreads();
        int ax = d / 9, ay = (d / 3) % 3, az = d % 3;
        int x = pv.y + ax - 1, y = pv.z + ay - 1, z = pv.w + az - 1;
        if (x >= 0 && x < GXD && y >= 0 && y < GYD && z >= 0 && z < GZD) {
            int m = g_map[((pv.x * GXD + x) * GYD + y) * GZD + z];
            if (m > 0) {
                const float* yr = &g_y[(m-1)*CC];
                #pragma unroll 8
                for (int c2 = 0; c2 < CC; c2 += 2) {
                    float y0 = yr[c2], y1 = yr[c2+1];
                    FMA2(acc0, pk(y0, y0), pk(sW[c2*NCL + op*2], sW[c2*NCL + op*2 + 1]),     acc0);
                    FMA2(acc1, pk(y1, y1), pk(sW[(c2+1)*NCL + op*2], sW[(c2+1)*NCL + op*2 + 1]), acc1);
                }
            }
        }
        __syncthreads();
    }
    float a0, a1, b0, b1;
    upk(a0, a1, acc0); upk(b0, b1, acc1);
    float2 res; res.x = a0 + b0; res.y = a1 + b1;
    *(float2*)&out[(n0 + v)*NCL + op*2] = res;
}

// --------------------------------------------------------------------------
extern "C" void kernel_launch(void* const* d_in, const int* in_sizes, int n_in,
                              void* d_out, int out_size) {
    const int*   idx  = (const int*)  d_in[0];
    const float* feat = (const float*)d_in[1];
    const float* cw1  = (const float*)d_in[2];
    const float* cb1  = (const float*)d_in[3];
    const float* cg1  = (const float*)d_in[4];
    const float* cbe1 = (const float*)d_in[5];
    const float* cw2  = (const float*)d_in[6];
    const float* cb2  = (const float*)d_in[7];
    const float* pw1  = (const float*)d_in[8];
    const float* pb1  = (const float*)d_in[9];
    const float* pg1  = (const float*)d_in[10];
    const float* pbe1 = (const float*)d_in[11];
    const float* pw2  = (const float*)d_in[12];
    const float* pb2  = (const float*)d_in[13];
    const float* wq   = (const float*)d_in[14];
    const float* bq   = (const float*)d_in[15];
    const float* wk   = (const float*)d_in[16];
    const float* bk   = (const float*)d_in[17];
    const float* wv   = (const float*)d_in[18];
    const float* bv   = (const float*)d_in[19];
    const float* wo   = (const float*)d_in[20];
    const float* bo   = (const float*)d_in[21];
    const float* ln_g = (const float*)d_in[22];
    const float* ln_b = (const float*)d_in[23];
    const float* segw = (const float*)d_in[24];
    const float* segb = (const float*)d_in[25];

    void* p_acc;
    cudaGetSymbolAddress(&p_acc, g_acc);

    constexpr int ATTN_SMEM = ATTN_FLOATS * 4;
    cudaFuncSetAttribute(k_attn, cudaFuncAttributeMaxDynamicSharedMemorySize, ATTN_SMEM);

    cudaMemsetAsync(p_acc, 0, sizeof(Acc), 0);

    k_prep    <<<1, 256>>>(idx, pw1, pb1, pg1, pbe1);
    k_sgemm1  <<<NSV, 512>>>(feat, cw1, cb1);
    k_gemm2kv <<<NSV, 512>>>(cw2, cb2, cg1, cbe1, wk, bk, wv, bv);
    k_attn    <<<NV/GQ, 256, ATTN_SMEM>>>(idx, feat, wq, bq, wo, bo, ln_g, ln_b, pw2, pb2);
    k_conv    <<<NV/32, 320>>>(idx, segw, segb, (float*)d_out);
}